// round 13
// baseline (speedup 1.0000x reference)
#include <cuda_runtime.h>
#include <cuda_fp16.h>
#include <cstdint>

#define N_NODES 8192
#define N_EDGES 32768
#define HID 128
#define N_SUB 512
#define N_GRAPH 32

// K' per layer (K + 2*ci, padded to multiple of 64)
#define KP0 2112
#define KP1 4160
#define KP2 8320
// B' buffer offsets (elems)
#define BOFF0 0
#define BOFF1 67584            // 2112*32
#define BOFF2 333824           // 67584 + 4160*64
#define BTOT  866304           // 333824 + 8320*64

// ---------------- device scratch (static; no allocations) ----------------
__device__ __half g_S[8192ull * 8320];   // [n][K'] fp16
__device__ __half g_Bh[BTOT];            // [K'][co] fp16, k-major
__device__ float g_xa[N_NODES * 64];
__device__ float g_xb[N_NODES * 64];
__device__ int   g_cnt[N_NODES + 1];     // edge counts; re-zeroed by k_scan after read
__device__ int   g_rowptr[N_NODES + 1];
__device__ int   g_fill[N_NODES];
__device__ int   g_eperm[N_EDGES];
__device__ float g_sub[N_SUB * 64];
__device__ float g_subcnt[N_SUB];

// ---------------- PTX helpers (baseline ISA only; no arch-suffix gating) --------
__device__ __forceinline__ uint32_t smem_u32(const void* p) {
    uint32_t a;
    asm("{ .reg .u64 t; cvta.to.shared.u64 t, %1; cvt.u32.u64 %0, t; }" : "=r"(a) : "l"(p));
    return a;
}
__device__ __forceinline__ void ldsm_x4(uint32_t& r0, uint32_t& r1, uint32_t& r2,
                                        uint32_t& r3, uint32_t addr) {
    asm volatile("ldmatrix.sync.aligned.m8n8.x4.shared.b16 {%0,%1,%2,%3}, [%4];"
                 : "=r"(r0), "=r"(r1), "=r"(r2), "=r"(r3) : "r"(addr));
}
__device__ __forceinline__ void ldsm_x4t(uint32_t& r0, uint32_t& r1, uint32_t& r2,
                                         uint32_t& r3, uint32_t addr) {
    asm volatile("ldmatrix.sync.aligned.m8n8.x4.trans.shared.b16 {%0,%1,%2,%3}, [%4];"
                 : "=r"(r0), "=r"(r1), "=r"(r2), "=r"(r3) : "r"(addr));
}
__device__ __forceinline__ void mma_f16(float& d0, float& d1, float& d2, float& d3,
                                        uint32_t a0, uint32_t a1, uint32_t a2, uint32_t a3,
                                        uint32_t b0, uint32_t b1) {
    asm volatile(
        "mma.sync.aligned.m16n8k16.row.col.f32.f16.f16.f32 "
        "{%0,%1,%2,%3}, {%4,%5,%6,%7}, {%8,%9}, {%0,%1,%2,%3};"
        : "+f"(d0), "+f"(d1), "+f"(d2), "+f"(d3)
        : "r"(a0), "r"(a1), "r"(a2), "r"(a3), "r"(b0), "r"(b1));
}
#define CP_ASYNC16(dst, src) \
    asm volatile("cp.async.cg.shared.global [%0], [%1], 16;" :: "r"(dst), "l"(src))
#define CP_COMMIT() asm volatile("cp.async.commit_group;" ::: "memory")
#define CP_WAIT2()  asm volatile("cp.async.wait_group 2;" ::: "memory")

// ---------------- fused prologue: zero pools + B' convert + edge count ---------
// g_cnt is pre-zeroed (BSS on first call; re-zeroed by k_scan on every call).
__global__ void k_init_bsplit_count(
    const int* __restrict__ ei,
    const float* __restrict__ W2_0, const float* __restrict__ b2_0, const float* __restrict__ rt_0,
    const float* __restrict__ W2_1, const float* __restrict__ b2_1, const float* __restrict__ rt_1,
    const float* __restrict__ W2_2, const float* __restrict__ b2_2, const float* __restrict__ rt_2)
{
    int idx = blockIdx.x * blockDim.x + threadIdx.x;
    if (idx < N_SUB * 64)   g_sub[idx] = 0.f;
    if (idx < N_SUB)        g_subcnt[idx] = 0.f;
    if (idx < N_EDGES) atomicAdd(&g_cnt[ei[N_EDGES + idx] + 1], 1);

    if (idx >= BTOT) return;
    int rel, ci, co, K;
    const float *W2, *b2, *rt;
    if (idx < BOFF1)      { rel = idx;         ci = 16; co = 32; K = 2048; W2 = W2_0; b2 = b2_0; rt = rt_0; }
    else if (idx < BOFF2) { rel = idx - BOFF1; ci = 32; co = 64; K = 4096; W2 = W2_1; b2 = b2_1; rt = rt_1; }
    else                  { rel = idx - BOFF2; ci = 64; co = 64; K = 8192; W2 = W2_2; b2 = b2_2; rt = rt_2; }
    int kk = rel / co, o = rel % co;
    float w;
    if (kk < K) {
        int i = kk >> 7, k = kk & 127;
        w = W2[(k * ci + i) * co + o];
    } else if (kk < K + ci) {
        w = b2[(kk - K) * co + o];
    } else if (kk < K + 2 * ci) {
        w = rt[(kk - K - ci) * co + o];
    } else {
        w = 0.f;
    }
    g_Bh[idx] = __float2half_rn(w);
}

// single-block scan: reads g_cnt, writes rowptr/fill, RE-ZEROES g_cnt for next call
__global__ void k_scan() {
    __shared__ int part[1024];
    int t = threadIdx.x;
    int v[8];
    int run = 0;
#pragma unroll
    for (int q = 0; q < 8; q++) {
        int pos = 1 + t * 8 + q;
        run += g_cnt[pos];
        g_cnt[pos] = 0;           // re-zero for the next graph replay
        v[q] = run;
    }
    part[t] = run;
    __syncthreads();
    int sum = run;
    for (int off = 1; off < 1024; off <<= 1) {
        int other = (t >= off) ? part[t - off] : 0;
        __syncthreads();
        sum += other;
        part[t] = sum;
        __syncthreads();
    }
    int add = sum - run;
#pragma unroll
    for (int q = 0; q < 8; q++) {
        int val = v[q] + add;
        int pos = 1 + t * 8 + q;
        g_rowptr[pos] = val;
        if (pos < N_NODES) g_fill[pos] = val;
    }
    if (t == 0) { g_rowptr[0] = 0; g_fill[0] = 0; }
}

__global__ void k_fill(const int* __restrict__ ei) {
    int e = blockIdx.x * blockDim.x + threadIdx.x;
    if (e < N_EDGES) {
        int d = ei[N_EDGES + e];
        int pos = atomicAdd(&g_fill[d], 1);
        g_eperm[pos] = e;
    }
}

// ---------------- scatter: S'[n] = [S | xs | x | 0pad] as fp16 ----------------
template <int CI>
__global__ __launch_bounds__(128) void k_scatter(
    const float* __restrict__ xcur, const int* __restrict__ ei,
    const float* __restrict__ eattr, const float* __restrict__ W1,
    const float* __restrict__ b1, int KP)
{
    constexpr int K = CI * 128;
    int n = blockIdx.x;
    int t = threadIdx.x;
    int w = t >> 5, lane = t & 31;
    __shared__ float sx[4][CI];
    __shared__ float sattr[4][5];

    float w1r[5];
#pragma unroll
    for (int j = 0; j < 5; j++) w1r[j] = W1[j * HID + t];
    float b1r = b1[t];

    float sacc[CI];
#pragma unroll
    for (int i = 0; i < CI; i++) sacc[i] = 0.f;
    float xsacc = 0.f;

    int beg = g_rowptr[n], end = g_rowptr[n + 1];
    for (int j0 = beg; j0 < end; j0 += 4) {
        int cnt = min(4, end - j0);
        if (w < cnt) {
            int e = g_eperm[j0 + w];
            int src = ei[e];
            if (lane < 5) sattr[w][lane] = eattr[e * 5 + lane];
#pragma unroll
            for (int i = lane; i < CI; i += 32) sx[w][i] = xcur[src * CI + i];
        }
        __syncthreads();
        for (int c = 0; c < cnt; c++) {
            float h = b1r;
#pragma unroll
            for (int q = 0; q < 5; q++) h += sattr[c][q] * w1r[q];
            h = fmaxf(h, 0.f);
#pragma unroll
            for (int i = 0; i < CI; i++) sacc[i] += h * sx[c][i];
            if (t < CI) xsacc += sx[c][t];
        }
        __syncthreads();
    }

    size_t base = (size_t)n * KP;
#pragma unroll
    for (int i = 0; i < CI; i++)
        g_S[base + (size_t)i * HID + t] = __float2half_rn(sacc[i]);
    int ext = KP - K;
    if (t < ext) {
        float v;
        if (t < CI) v = xsacc;
        else if (t < 2 * CI) v = xcur[n * CI + (t - CI)];
        else v = 0.f;
        g_S[base + K + t] = __float2half_rn(v);
    }
}

// ---------------- GEMM CO=32 (layer 1): fp16 single product ----------------
__global__ __launch_bounds__(256) void k_gemm32(int KP, int boff,
                                                float* __restrict__ xnext,
                                                const float* __restrict__ bias)
{
    constexpr int CO = 32;
    constexpr int AP = 72;
    constexpr int BP = CO + 8;                 // 40
    constexpr uint32_t A_OFF = 0;
    constexpr uint32_t BH_OFF = 64 * AP * 2;   // 9216
    constexpr uint32_t STAGE = BH_OFF + 64 * BP * 2;    // 14336
    constexpr int NSTAGE = 4;

    extern __shared__ char smem[];
    const uint32_t sb = smem_u32(smem);

    const int t = threadIdx.x;
    const int wid = t >> 5, lane = t & 31;
    const int wm = wid & 3;
    const int wn = wid >> 2;
    const int m0 = blockIdx.x * 64;

    float acc[2][4];
#pragma unroll
    for (int i = 0; i < 2; i++)
#pragma unroll
        for (int j = 0; j < 4; j++) acc[i][j] = 0.f;

    const int nIter = KP / 64;

    auto issue = [&](int sg, int kt) {
        uint32_t s0 = sb + sg * STAGE;
#pragma unroll
        for (int p = 0; p < 2; p++) {
            int c = t + 256 * p;
            int row = c >> 3, cc = c & 7;
            uint32_t d = s0 + (uint32_t)(row * AP + cc * 8) * 2u;
            CP_ASYNC16(d + A_OFF, &g_S[(size_t)(m0 + row) * KP + kt + cc * 8]);
        }
        {
            int c = t;
            int row = c >> 2, cc = c & 3;
            uint32_t d = s0 + (uint32_t)(row * BP + cc * 8) * 2u;
            CP_ASYNC16(d + BH_OFF, &g_Bh[boff + (size_t)(kt + row) * CO + cc * 8]);
        }
    };

#pragma unroll
    for (int s = 0; s < NSTAGE - 1; s++) { issue(s, s * 64); CP_COMMIT(); }

    for (int it = 0; it < nIter; it++) {
        CP_WAIT2();
        __syncthreads();
        if (it + NSTAGE - 1 < nIter) issue((it + NSTAGE - 1) & (NSTAGE - 1),
                                           (it + NSTAGE - 1) * 64);
        CP_COMMIT();

        uint32_t s0 = sb + (it & (NSTAGE - 1)) * STAGE;
#pragma unroll
        for (int ks = 0; ks < 4; ks++) {
            uint32_t a_off = s0 + (uint32_t)((wm * 16 + (lane & 15)) * AP +
                                             ks * 16 + (lane >> 4) * 8) * 2u;
            uint32_t a0, a1, a2, a3;
            ldsm_x4(a0, a1, a2, a3, a_off + A_OFF);
            {
                int nb = wn * 16;
                uint32_t b_off = s0 + (uint32_t)((ks * 16 + (lane & 15)) * BP +
                                                 nb + (lane >> 4) * 8) * 2u;
                uint32_t bh0, bh1, bh2, bh3;
                ldsm_x4t(bh0, bh1, bh2, bh3, b_off + BH_OFF);
                mma_f16(acc[0][0], acc[0][1], acc[0][2], acc[0][3], a0, a1, a2, a3, bh0, bh1);
                mma_f16(acc[1][0], acc[1][1], acc[1][2], acc[1][3], a0, a1, a2, a3, bh2, bh3);
            }
        }
    }

    const int row0 = lane >> 2;
    const int col0 = (lane & 3) * 2;
#pragma unroll
    for (int nt = 0; nt < 2; nt++) {
        int m = m0 + wm * 16 + row0;
        int c = wn * 16 + nt * 8 + col0;
        float b0 = bias[c], b1v = bias[c + 1];
        float v0 = acc[nt][0] + b0, v1 = acc[nt][1] + b1v;
        float v2 = acc[nt][2] + b0, v3 = acc[nt][3] + b1v;
        v0 = (v0 > 0.f) ? v0 : expm1f(v0);
        v1 = (v1 > 0.f) ? v1 : expm1f(v1);
        v2 = (v2 > 0.f) ? v2 : expm1f(v2);
        v3 = (v3 > 0.f) ? v3 : expm1f(v3);
        *(float2*)&xnext[(size_t)m * CO + c] = make_float2(v0, v1);
        *(float2*)&xnext[(size_t)(m + 8) * CO + c] = make_float2(v2, v3);
    }
}

// ---------------- GEMM CO=64: m32n32 warp tile, 2-way split-K, single product --
// do_pool: fuse subgraph mean-pool accumulation (layer 3) and skip xnext stores.
__global__ __launch_bounds__(256) void k_gemm64(int KP, int boff,
                                                float* __restrict__ xnext,
                                                const float* __restrict__ bias,
                                                const int* __restrict__ n2s,
                                                int do_pool)
{
    constexpr int CO = 64;
    constexpr int AP = 72;
    constexpr int BP = CO + 8;                 // 72
    constexpr uint32_t A_OFF = 0;
    constexpr uint32_t BH_OFF = 64 * AP * 2;   // 9216
    constexpr uint32_t STAGE = BH_OFF + 64 * BP * 2;    // 18432
    constexpr int NSTAGE = 4;

    extern __shared__ char smem[];
    const uint32_t sb = smem_u32(smem);

    const int t = threadIdx.x;
    const int wid = t >> 5, lane = t & 31;
    const int wk = wid >> 2;
    const int wm = (wid >> 1) & 1;
    const int wn = wid & 1;
    const int m0 = blockIdx.x * 64;

    float acc[8][4];
#pragma unroll
    for (int i = 0; i < 8; i++)
#pragma unroll
        for (int j = 0; j < 4; j++) acc[i][j] = 0.f;

    const int nIter = KP / 64;

    auto issue = [&](int sg, int kt) {
        uint32_t s0 = sb + sg * STAGE;
#pragma unroll
        for (int p = 0; p < 2; p++) {
            int c = t + 256 * p;
            int row = c >> 3, cc = c & 7;
            uint32_t d = s0 + (uint32_t)(row * AP + cc * 8) * 2u;
            CP_ASYNC16(d + A_OFF, &g_S[(size_t)(m0 + row) * KP + kt + cc * 8]);
        }
#pragma unroll
        for (int p = 0; p < 2; p++) {
            int c = t + 256 * p;
            int row = c >> 3, cc = c & 7;
            uint32_t d = s0 + (uint32_t)(row * BP + cc * 8) * 2u;
            CP_ASYNC16(d + BH_OFF, &g_Bh[boff + (size_t)(kt + row) * CO + cc * 8]);
        }
    };

#pragma unroll
    for (int s = 0; s < NSTAGE - 1; s++) { issue(s, s * 64); CP_COMMIT(); }

    for (int it = 0; it < nIter; it++) {
        CP_WAIT2();
        __syncthreads();
        if (it + NSTAGE - 1 < nIter) issue((it + NSTAGE - 1) & (NSTAGE - 1),
                                           (it + NSTAGE - 1) * 64);
        CP_COMMIT();

        uint32_t s0 = sb + (it & (NSTAGE - 1)) * STAGE;
#pragma unroll
        for (int ks2 = 0; ks2 < 2; ks2++) {
            int kk = wk * 32 + ks2 * 16;
            uint32_t ah[2][4];
#pragma unroll
            for (int mt = 0; mt < 2; mt++) {
                uint32_t a_off = s0 + (uint32_t)((wm * 32 + mt * 16 + (lane & 15)) * AP +
                                                 kk + (lane >> 4) * 8) * 2u;
                ldsm_x4(ah[mt][0], ah[mt][1], ah[mt][2], ah[mt][3], a_off + A_OFF);
            }
            uint32_t bh[2][4];
#pragma unroll
            for (int np = 0; np < 2; np++) {
                int nb = wn * 32 + np * 16;
                uint32_t b_off = s0 + (uint32_t)((kk + (lane & 15)) * BP +
                                                 nb + (lane >> 4) * 8) * 2u;
                ldsm_x4t(bh[np][0], bh[np][1], bh[np][2], bh[np][3], b_off + BH_OFF);
            }
#pragma unroll
            for (int mt = 0; mt < 2; mt++) {
#pragma unroll
                for (int np = 0; np < 2; np++) {
                    float* c0 = acc[mt * 4 + np * 2 + 0];
                    float* c1 = acc[mt * 4 + np * 2 + 1];
                    mma_f16(c0[0], c0[1], c0[2], c0[3],
                            ah[mt][0], ah[mt][1], ah[mt][2], ah[mt][3], bh[np][0], bh[np][1]);
                    mma_f16(c1[0], c1[1], c1[2], c1[3],
                            ah[mt][0], ah[mt][1], ah[mt][2], ah[mt][3], bh[np][2], bh[np][3]);
                }
            }
        }
    }

    // ---- split-K reduction: wk=1 warps dump acc to smem, wk=0 warps add ----
    __syncthreads();
    {
        float* red = (float*)smem;
        int pair = wm * 2 + wn;
        if (wk == 1) {
#pragma unroll
            for (int j = 0; j < 8; j++)
#pragma unroll
                for (int q = 0; q < 4; q++)
                    red[pair * 1024 + (j * 4 + q) * 32 + lane] = acc[j][q];
        }
        __syncthreads();
        if (wk == 0) {
#pragma unroll
            for (int j = 0; j < 8; j++)
#pragma unroll
                for (int q = 0; q < 4; q++)
                    acc[j][q] += red[pair * 1024 + (j * 4 + q) * 32 + lane];
        }
    }

    if (wk == 0) {
        const int row0 = lane >> 2;
        const int col0 = (lane & 3) * 2;
#pragma unroll
        for (int mt = 0; mt < 2; mt++) {
            int mA = m0 + wm * 32 + mt * 16 + row0;
            int mB = mA + 8;
            int sA = 0, sB = 0;
            if (do_pool) { sA = n2s[mA]; sB = n2s[mB]; }
#pragma unroll
            for (int np = 0; np < 2; np++) {
#pragma unroll
                for (int h = 0; h < 2; h++) {
                    float* a = acc[mt * 4 + np * 2 + h];
                    int c = wn * 32 + np * 16 + h * 8 + col0;
                    float b0 = bias[c], b1v = bias[c + 1];
                    float v0 = a[0] + b0, v1 = a[1] + b1v;
                    float v2 = a[2] + b0, v3 = a[3] + b1v;
                    v0 = (v0 > 0.f) ? v0 : expm1f(v0);
                    v1 = (v1 > 0.f) ? v1 : expm1f(v1);
                    v2 = (v2 > 0.f) ? v2 : expm1f(v2);
                    v3 = (v3 > 0.f) ? v3 : expm1f(v3);
                    if (do_pool) {
                        atomicAdd(&g_sub[sA * 64 + c],     v0);
                        atomicAdd(&g_sub[sA * 64 + c + 1], v1);
                        atomicAdd(&g_sub[sB * 64 + c],     v2);
                        atomicAdd(&g_sub[sB * 64 + c + 1], v3);
                        if (wn == 0 && np == 0 && h == 0 && col0 == 0) {
                            atomicAdd(&g_subcnt[sA], 1.f);
                            atomicAdd(&g_subcnt[sB], 1.f);
                        }
                    } else {
                        *(float2*)&xnext[(size_t)mA * CO + c] = make_float2(v0, v1);
                        *(float2*)&xnext[(size_t)mB * CO + c] = make_float2(v2, v3);
                    }
                }
            }
        }
    }
}

// ---------------- fused pool2 + final MLP (single block) ----------------
__global__ void k_fc(const int* __restrict__ s2g,
                     const float* __restrict__ fc1w, const float* __restrict__ fc1b,
                     const float* __restrict__ fc2w, const float* __restrict__ fc2b,
                     const float* __restrict__ fc3w, const float* __restrict__ fc3b,
                     float* __restrict__ out)
{
    __shared__ float gg[N_GRAPH * 64];
    __shared__ float gcnt[N_GRAPH];
    __shared__ float hg[N_GRAPH * 64];
    __shared__ float h1[N_GRAPH * 32];
    __shared__ float h2[N_GRAPH * 16];
    int t = threadIdx.x;  // 256

    for (int idx = t; idx < N_GRAPH * 64; idx += 256) gg[idx] = 0.f;
    if (t < N_GRAPH) gcnt[t] = 0.f;
    __syncthreads();

    // subgraph means -> graph sums (smem atomics)
    for (int idx = t; idx < N_SUB * 64; idx += 256) {
        int s = idx / 64, o = idx % 64;
        float m = g_sub[idx] / fmaxf(g_subcnt[s], 1.f);
        atomicAdd(&gg[s2g[s] * 64 + o], m);
    }
    for (int s = t; s < N_SUB; s += 256)
        atomicAdd(&gcnt[s2g[s]], 1.f);
    __syncthreads();

    for (int idx = t; idx < N_GRAPH * 64; idx += 256) {
        int g = idx / 64;
        hg[idx] = gg[idx] / fmaxf(gcnt[g], 1.f);
    }
    __syncthreads();
    for (int idx = t; idx < N_GRAPH * 32; idx += 256) {
        int g = idx / 32, o = idx % 32;
        float v = fc1b[o];
        for (int i = 0; i < 64; i++) v += hg[g * 64 + i] * fc1w[i * 32 + o];
        h1[idx] = (v > 0.f) ? v : expm1f(v);
    }
    __syncthreads();
    for (int idx = t; idx < N_GRAPH * 16; idx += 256) {
        int g = idx / 16, o = idx % 16;
        float v = fc2b[o];
        for (int i = 0; i < 32; i++) v += h1[g * 32 + i] * fc2w[i * 16 + o];
        h2[idx] = (v > 0.f) ? v : expm1f(v);
    }
    __syncthreads();
    if (t < N_GRAPH) {
        float v = fc3b[0];
        for (int i = 0; i < 16; i++) v += h2[t * 16 + i] * fc3w[i];
        out[t] = v;
    }
}

// ---------------- host launch ----------------
extern "C" void kernel_launch(void* const* d_in, const int* in_sizes, int n_in,
                              void* d_out, int out_size)
{
    const float* x     = (const float*)d_in[0];
    const int*   ei    = (const int*)d_in[1];
    const float* eattr = (const float*)d_in[2];
    const int*   n2s   = (const int*)d_in[3];
    const int*   s2g   = (const int*)d_in[4];
    const float* W1[3]   = {(const float*)d_in[5],  (const float*)d_in[11], (const float*)d_in[17]};
    const float* b1[3]   = {(const float*)d_in[6],  (const float*)d_in[12], (const float*)d_in[18]};
    const float* W2[3]   = {(const float*)d_in[7],  (const float*)d_in[13], (const float*)d_in[19]};
    const float* b2[3]   = {(const float*)d_in[8],  (const float*)d_in[14], (const float*)d_in[20]};
    const float* root[3] = {(const float*)d_in[9],  (const float*)d_in[15], (const float*)d_in[21]};
    const float* bias[3] = {(const float*)d_in[10], (const float*)d_in[16], (const float*)d_in[22]};
    const float* fc1w = (const float*)d_in[23];
    const float* fc1b = (const float*)d_in[24];
    const float* fc2w = (const float*)d_in[25];
    const float* fc2b = (const float*)d_in[26];
    const float* fc3w = (const float*)d_in[27];
    const float* fc3b = (const float*)d_in[28];
    float* out = (float*)d_out;

    float *xa, *xb;
    cudaGetSymbolAddress((void**)&xa, g_xa);
    cudaGetSymbolAddress((void**)&xb, g_xb);

    // dynamic smem: 4 stages. CO=64: 4*18432=73728B; CO=32: 4*14336=57344B
    static bool attr_set = false;
    if (!attr_set) {
        cudaFuncSetAttribute(k_gemm64, cudaFuncAttributeMaxDynamicSharedMemorySize, 73728);
        cudaFuncSetAttribute(k_gemm32, cudaFuncAttributeMaxDynamicSharedMemorySize, 57344);
        attr_set = true;
    }

    // prologue: fused init+bsplit+count, then scan + fill
    k_init_bsplit_count<<<(BTOT + 255) / 256, 256>>>(ei,
                                                     W2[0], b2[0], root[0],
                                                     W2[1], b2[1], root[1],
                                                     W2[2], b2[2], root[2]);
    k_scan<<<1, 1024>>>();
    k_fill<<<N_EDGES / 256, 256>>>(ei);

    const int KP[3] = {KP0, KP1, KP2};
    const int BOFF[3] = {BOFF0, BOFF1, BOFF2};
    const float* xcur = x;
    float* xnext = xa;

    for (int l = 0; l < 3; l++) {
        if (l == 0)      k_scatter<16><<<N_NODES, 128>>>(xcur, ei, eattr, W1[l], b1[l], KP[l]);
        else if (l == 1) k_scatter<32><<<N_NODES, 128>>>(xcur, ei, eattr, W1[l], b1[l], KP[l]);
        else             k_scatter<64><<<N_NODES, 128>>>(xcur, ei, eattr, W1[l], b1[l], KP[l]);

        if (l == 0)
            k_gemm32<<<N_NODES / 64, 256, 57344>>>(KP[l], BOFF[l], xnext, bias[l]);
        else
            k_gemm64<<<N_NODES / 64, 256, 73728>>>(KP[l], BOFF[l], xnext, bias[l],
                                                   n2s, (l == 2) ? 1 : 0);

        xcur = xnext;
        xnext = (xnext == xa) ? xb : xa;
    }

    // fused pool2 + MLP head (pool1 fused into layer-3 GEMM epilogue)
    k_fc<<<1, 256>>>(s2g, fc1w, fc1b, fc2w, fc2b, fc3w, fc3b, out);
}

// round 14
// speedup vs baseline: 1.2109x; 1.2109x over previous
#include <cuda_runtime.h>
#include <cuda_fp16.h>
#include <cstdint>

#define N_NODES 8192
#define N_EDGES 32768
#define HID 128
#define N_SUB 512
#define N_GRAPH 32

// K' per layer (K + 2*ci, padded to multiple of 64)
#define KP0 2112
#define KP1 4160
#define KP2 8320
// B' buffer offsets (elems)
#define BOFF0 0
#define BOFF1 67584            // 2112*32
#define BOFF2 333824           // 67584 + 4160*64
#define BTOT  866304           // 333824 + 8320*64

#define NODES_PER_BLK 8

// ---------------- device scratch (static; no allocations) ----------------
__device__ __half g_S[8192ull * 8320];   // [n][K'] fp16
__device__ __half g_Bh[BTOT];            // [K'][co] fp16, k-major
__device__ float g_xa[N_NODES * 64];
__device__ float g_xb[N_NODES * 64];
__device__ int   g_rowptr[N_NODES + 1];
__device__ int   g_fill[N_NODES];
__device__ int   g_eperm[N_EDGES];
__device__ float g_sub[N_SUB * 64];
__device__ float g_subcnt[N_SUB];
__device__ float g_graph[N_GRAPH * 64];
__device__ float g_graphcnt[N_GRAPH];

// ---------------- PTX helpers (baseline ISA only; no arch-suffix gating) --------
__device__ __forceinline__ uint32_t smem_u32(const void* p) {
    uint32_t a;
    asm("{ .reg .u64 t; cvta.to.shared.u64 t, %1; cvt.u32.u64 %0, t; }" : "=r"(a) : "l"(p));
    return a;
}
__device__ __forceinline__ void ldsm_x4(uint32_t& r0, uint32_t& r1, uint32_t& r2,
                                        uint32_t& r3, uint32_t addr) {
    asm volatile("ldmatrix.sync.aligned.m8n8.x4.shared.b16 {%0,%1,%2,%3}, [%4];"
                 : "=r"(r0), "=r"(r1), "=r"(r2), "=r"(r3) : "r"(addr));
}
__device__ __forceinline__ void ldsm_x4t(uint32_t& r0, uint32_t& r1, uint32_t& r2,
                                         uint32_t& r3, uint32_t addr) {
    asm volatile("ldmatrix.sync.aligned.m8n8.x4.trans.shared.b16 {%0,%1,%2,%3}, [%4];"
                 : "=r"(r0), "=r"(r1), "=r"(r2), "=r"(r3) : "r"(addr));
}
__device__ __forceinline__ void mma_f16(float& d0, float& d1, float& d2, float& d3,
                                        uint32_t a0, uint32_t a1, uint32_t a2, uint32_t a3,
                                        uint32_t b0, uint32_t b1) {
    asm volatile(
        "mma.sync.aligned.m16n8k16.row.col.f32.f16.f16.f32 "
        "{%0,%1,%2,%3}, {%4,%5,%6,%7}, {%8,%9}, {%0,%1,%2,%3};"
        : "+f"(d0), "+f"(d1), "+f"(d2), "+f"(d3)
        : "r"(a0), "r"(a1), "r"(a2), "r"(a3), "r"(b0), "r"(b1));
}
#define CP_ASYNC16(dst, src) \
    asm volatile("cp.async.cg.shared.global [%0], [%1], 16;" :: "r"(dst), "l"(src))
#define CP_COMMIT() asm volatile("cp.async.commit_group;" ::: "memory")
#define CP_WAIT2()  asm volatile("cp.async.wait_group 2;" ::: "memory")

// ---------------- init + B' conversion fused (both pure writers) ----------------
__global__ void k_init_bsplit(
    const float* __restrict__ W2_0, const float* __restrict__ b2_0, const float* __restrict__ rt_0,
    const float* __restrict__ W2_1, const float* __restrict__ b2_1, const float* __restrict__ rt_1,
    const float* __restrict__ W2_2, const float* __restrict__ b2_2, const float* __restrict__ rt_2)
{
    int idx = blockIdx.x * blockDim.x + threadIdx.x;
    if (idx <= N_NODES) g_rowptr[idx] = 0;
    if (idx < N_SUB * 64)   g_sub[idx] = 0.f;
    if (idx < N_SUB)        g_subcnt[idx] = 0.f;
    if (idx < N_GRAPH * 64) g_graph[idx] = 0.f;
    if (idx < N_GRAPH)      g_graphcnt[idx] = 0.f;

    if (idx >= BTOT) return;
    int rel, ci, co, K;
    const float *W2, *b2, *rt;
    if (idx < BOFF1)      { rel = idx;         ci = 16; co = 32; K = 2048; W2 = W2_0; b2 = b2_0; rt = rt_0; }
    else if (idx < BOFF2) { rel = idx - BOFF1; ci = 32; co = 64; K = 4096; W2 = W2_1; b2 = b2_1; rt = rt_1; }
    else                  { rel = idx - BOFF2; ci = 64; co = 64; K = 8192; W2 = W2_2; b2 = b2_2; rt = rt_2; }
    int kk = rel / co, o = rel % co;
    float w;
    if (kk < K) {
        int i = kk >> 7, k = kk & 127;
        w = W2[(k * ci + i) * co + o];
    } else if (kk < K + ci) {
        w = b2[(kk - K) * co + o];
    } else if (kk < K + 2 * ci) {
        w = rt[(kk - K - ci) * co + o];
    } else {
        w = 0.f;
    }
    g_Bh[idx] = __float2half_rn(w);
}

__global__ void k_count(const int* __restrict__ ei) {
    int e = blockIdx.x * blockDim.x + threadIdx.x;
    if (e < N_EDGES) atomicAdd(&g_rowptr[ei[N_EDGES + e] + 1], 1);
}

__global__ void k_scan() {
    __shared__ int part[1024];
    int t = threadIdx.x;
    int v[8];
    int run = 0;
#pragma unroll
    for (int q = 0; q < 8; q++) { run += g_rowptr[1 + t * 8 + q]; v[q] = run; }
    part[t] = run;
    __syncthreads();
    int sum = run;
    for (int off = 1; off < 1024; off <<= 1) {
        int other = (t >= off) ? part[t - off] : 0;
        __syncthreads();
        sum += other;
        part[t] = sum;
        __syncthreads();
    }
    int add = sum - run;
#pragma unroll
    for (int q = 0; q < 8; q++) {
        int val = v[q] + add;
        int pos = 1 + t * 8 + q;
        g_rowptr[pos] = val;
        if (pos < N_NODES) g_fill[pos] = val;
    }
    if (t == 0) { g_rowptr[0] = 0; g_fill[0] = 0; }
}

__global__ void k_fill(const int* __restrict__ ei) {
    int e = blockIdx.x * blockDim.x + threadIdx.x;
    if (e < N_EDGES) {
        int d = ei[N_EDGES + e];
        int pos = atomicAdd(&g_fill[d], 1);
        g_eperm[pos] = e;
    }
}

// ---------------- persistent scatter: each block processes NODES_PER_BLK nodes --
// W1/b1 register loads amortized across nodes; per-node logic identical to R12.
template <int CI>
__global__ __launch_bounds__(128) void k_scatter(
    const float* __restrict__ xcur, const int* __restrict__ ei,
    const float* __restrict__ eattr, const float* __restrict__ W1,
    const float* __restrict__ b1, int KP)
{
    constexpr int K = CI * 128;
    int t = threadIdx.x;
    int w = t >> 5, lane = t & 31;
    __shared__ float sx[4][CI];
    __shared__ float sattr[4][5];

    float w1r[5];
#pragma unroll
    for (int j = 0; j < 5; j++) w1r[j] = W1[j * HID + t];
    float b1r = b1[t];

    int n0 = blockIdx.x * NODES_PER_BLK;
    for (int nn = 0; nn < NODES_PER_BLK; nn++) {
        int n = n0 + nn;

        float sacc[CI];
#pragma unroll
        for (int i = 0; i < CI; i++) sacc[i] = 0.f;
        float xsacc = 0.f;

        int beg = g_rowptr[n], end = g_rowptr[n + 1];
        for (int j0 = beg; j0 < end; j0 += 4) {
            int cnt = min(4, end - j0);
            if (w < cnt) {
                int e = g_eperm[j0 + w];
                int src = ei[e];
                if (lane < 5) sattr[w][lane] = eattr[e * 5 + lane];
#pragma unroll
                for (int i = lane; i < CI; i += 32) sx[w][i] = xcur[src * CI + i];
            }
            __syncthreads();
            for (int c = 0; c < cnt; c++) {
                float h = b1r;
#pragma unroll
                for (int q = 0; q < 5; q++) h += sattr[c][q] * w1r[q];
                h = fmaxf(h, 0.f);
#pragma unroll
                for (int i = 0; i < CI; i++) sacc[i] += h * sx[c][i];
                if (t < CI) xsacc += sx[c][t];
            }
            __syncthreads();
        }

        size_t base = (size_t)n * KP;
#pragma unroll
        for (int i = 0; i < CI; i++)
            g_S[base + (size_t)i * HID + t] = __float2half_rn(sacc[i]);
        int ext = KP - K;
        if (t < ext) {
            float v;
            if (t < CI) v = xsacc;
            else if (t < 2 * CI) v = xcur[n * CI + (t - CI)];
            else v = 0.f;
            g_S[base + K + t] = __float2half_rn(v);
        }
    }
}

// ---------------- GEMM CO=32 (layer 1): fp16 single product ----------------
__global__ __launch_bounds__(256) void k_gemm32(int KP, int boff,
                                                float* __restrict__ xnext,
                                                const float* __restrict__ bias)
{
    constexpr int CO = 32;
    constexpr int AP = 72;
    constexpr int BP = CO + 8;                 // 40
    constexpr uint32_t A_OFF = 0;
    constexpr uint32_t BH_OFF = 64 * AP * 2;   // 9216
    constexpr uint32_t STAGE = BH_OFF + 64 * BP * 2;    // 14336
    constexpr int NSTAGE = 4;

    extern __shared__ char smem[];
    const uint32_t sb = smem_u32(smem);

    const int t = threadIdx.x;
    const int wid = t >> 5, lane = t & 31;
    const int wm = wid & 3;
    const int wn = wid >> 2;
    const int m0 = blockIdx.x * 64;

    float acc[2][4];
#pragma unroll
    for (int i = 0; i < 2; i++)
#pragma unroll
        for (int j = 0; j < 4; j++) acc[i][j] = 0.f;

    const int nIter = KP / 64;

    auto issue = [&](int sg, int kt) {
        uint32_t s0 = sb + sg * STAGE;
#pragma unroll
        for (int p = 0; p < 2; p++) {
            int c = t + 256 * p;
            int row = c >> 3, cc = c & 7;
            uint32_t d = s0 + (uint32_t)(row * AP + cc * 8) * 2u;
            CP_ASYNC16(d + A_OFF, &g_S[(size_t)(m0 + row) * KP + kt + cc * 8]);
        }
        {
            int c = t;
            int row = c >> 2, cc = c & 3;
            uint32_t d = s0 + (uint32_t)(row * BP + cc * 8) * 2u;
            CP_ASYNC16(d + BH_OFF, &g_Bh[boff + (size_t)(kt + row) * CO + cc * 8]);
        }
    };

#pragma unroll
    for (int s = 0; s < NSTAGE - 1; s++) { issue(s, s * 64); CP_COMMIT(); }

    for (int it = 0; it < nIter; it++) {
        CP_WAIT2();
        __syncthreads();
        if (it + NSTAGE - 1 < nIter) issue((it + NSTAGE - 1) & (NSTAGE - 1),
                                           (it + NSTAGE - 1) * 64);
        CP_COMMIT();

        uint32_t s0 = sb + (it & (NSTAGE - 1)) * STAGE;
#pragma unroll
        for (int ks = 0; ks < 4; ks++) {
            uint32_t a_off = s0 + (uint32_t)((wm * 16 + (lane & 15)) * AP +
                                             ks * 16 + (lane >> 4) * 8) * 2u;
            uint32_t a0, a1, a2, a3;
            ldsm_x4(a0, a1, a2, a3, a_off + A_OFF);
            {
                int nb = wn * 16;
                uint32_t b_off = s0 + (uint32_t)((ks * 16 + (lane & 15)) * BP +
                                                 nb + (lane >> 4) * 8) * 2u;
                uint32_t bh0, bh1, bh2, bh3;
                ldsm_x4t(bh0, bh1, bh2, bh3, b_off + BH_OFF);
                mma_f16(acc[0][0], acc[0][1], acc[0][2], acc[0][3], a0, a1, a2, a3, bh0, bh1);
                mma_f16(acc[1][0], acc[1][1], acc[1][2], acc[1][3], a0, a1, a2, a3, bh2, bh3);
            }
        }
    }

    const int row0 = lane >> 2;
    const int col0 = (lane & 3) * 2;
#pragma unroll
    for (int nt = 0; nt < 2; nt++) {
        int m = m0 + wm * 16 + row0;
        int c = wn * 16 + nt * 8 + col0;
        float b0 = bias[c], b1v = bias[c + 1];
        float v0 = acc[nt][0] + b0, v1 = acc[nt][1] + b1v;
        float v2 = acc[nt][2] + b0, v3 = acc[nt][3] + b1v;
        v0 = (v0 > 0.f) ? v0 : expm1f(v0);
        v1 = (v1 > 0.f) ? v1 : expm1f(v1);
        v2 = (v2 > 0.f) ? v2 : expm1f(v2);
        v3 = (v3 > 0.f) ? v3 : expm1f(v3);
        *(float2*)&xnext[(size_t)m * CO + c] = make_float2(v0, v1);
        *(float2*)&xnext[(size_t)(m + 8) * CO + c] = make_float2(v2, v3);
    }
}

// ---------------- GEMM CO=64: m32n32 warp tile, 2-way split-K, single product --
__global__ __launch_bounds__(256) void k_gemm64(int KP, int boff,
                                                float* __restrict__ xnext,
                                                const float* __restrict__ bias)
{
    constexpr int CO = 64;
    constexpr int AP = 72;
    constexpr int BP = CO + 8;                 // 72
    constexpr uint32_t A_OFF = 0;
    constexpr uint32_t BH_OFF = 64 * AP * 2;   // 9216
    constexpr uint32_t STAGE = BH_OFF + 64 * BP * 2;    // 18432
    constexpr int NSTAGE = 4;

    extern __shared__ char smem[];
    const uint32_t sb = smem_u32(smem);

    const int t = threadIdx.x;
    const int wid = t >> 5, lane = t & 31;
    const int wk = wid >> 2;
    const int wm = (wid >> 1) & 1;
    const int wn = wid & 1;
    const int m0 = blockIdx.x * 64;

    float acc[8][4];
#pragma unroll
    for (int i = 0; i < 8; i++)
#pragma unroll
        for (int j = 0; j < 4; j++) acc[i][j] = 0.f;

    const int nIter = KP / 64;

    auto issue = [&](int sg, int kt) {
        uint32_t s0 = sb + sg * STAGE;
#pragma unroll
        for (int p = 0; p < 2; p++) {
            int c = t + 256 * p;
            int row = c >> 3, cc = c & 7;
            uint32_t d = s0 + (uint32_t)(row * AP + cc * 8) * 2u;
            CP_ASYNC16(d + A_OFF, &g_S[(size_t)(m0 + row) * KP + kt + cc * 8]);
        }
#pragma unroll
        for (int p = 0; p < 2; p++) {
            int c = t + 256 * p;
            int row = c >> 3, cc = c & 7;
            uint32_t d = s0 + (uint32_t)(row * BP + cc * 8) * 2u;
            CP_ASYNC16(d + BH_OFF, &g_Bh[boff + (size_t)(kt + row) * CO + cc * 8]);
        }
    };

#pragma unroll
    for (int s = 0; s < NSTAGE - 1; s++) { issue(s, s * 64); CP_COMMIT(); }

    for (int it = 0; it < nIter; it++) {
        CP_WAIT2();
        __syncthreads();
        if (it + NSTAGE - 1 < nIter) issue((it + NSTAGE - 1) & (NSTAGE - 1),
                                           (it + NSTAGE - 1) * 64);
        CP_COMMIT();

        uint32_t s0 = sb + (it & (NSTAGE - 1)) * STAGE;
#pragma unroll
        for (int ks2 = 0; ks2 < 2; ks2++) {
            int kk = wk * 32 + ks2 * 16;
            uint32_t ah[2][4];
#pragma unroll
            for (int mt = 0; mt < 2; mt++) {
                uint32_t a_off = s0 + (uint32_t)((wm * 32 + mt * 16 + (lane & 15)) * AP +
                                                 kk + (lane >> 4) * 8) * 2u;
                ldsm_x4(ah[mt][0], ah[mt][1], ah[mt][2], ah[mt][3], a_off + A_OFF);
            }
            uint32_t bh[2][4];
#pragma unroll
            for (int np = 0; np < 2; np++) {
                int nb = wn * 32 + np * 16;
                uint32_t b_off = s0 + (uint32_t)((kk + (lane & 15)) * BP +
                                                 nb + (lane >> 4) * 8) * 2u;
                ldsm_x4t(bh[np][0], bh[np][1], bh[np][2], bh[np][3], b_off + BH_OFF);
            }
#pragma unroll
            for (int mt = 0; mt < 2; mt++) {
#pragma unroll
                for (int np = 0; np < 2; np++) {
                    float* c0 = acc[mt * 4 + np * 2 + 0];
                    float* c1 = acc[mt * 4 + np * 2 + 1];
                    mma_f16(c0[0], c0[1], c0[2], c0[3],
                            ah[mt][0], ah[mt][1], ah[mt][2], ah[mt][3], bh[np][0], bh[np][1]);
                    mma_f16(c1[0], c1[1], c1[2], c1[3],
                            ah[mt][0], ah[mt][1], ah[mt][2], ah[mt][3], bh[np][2], bh[np][3]);
                }
            }
        }
    }

    // ---- split-K reduction: wk=1 warps dump acc to smem, wk=0 warps add ----
    __syncthreads();
    {
        float* red = (float*)smem;
        int pair = wm * 2 + wn;
        if (wk == 1) {
#pragma unroll
            for (int j = 0; j < 8; j++)
#pragma unroll
                for (int q = 0; q < 4; q++)
                    red[pair * 1024 + (j * 4 + q) * 32 + lane] = acc[j][q];
        }
        __syncthreads();
        if (wk == 0) {
#pragma unroll
            for (int j = 0; j < 8; j++)
#pragma unroll
                for (int q = 0; q < 4; q++)
                    acc[j][q] += red[pair * 1024 + (j * 4 + q) * 32 + lane];
        }
    }

    if (wk == 0) {
        const int row0 = lane >> 2;
        const int col0 = (lane & 3) * 2;
#pragma unroll
        for (int mt = 0; mt < 2; mt++) {
#pragma unroll
            for (int np = 0; np < 2; np++) {
#pragma unroll
                for (int h = 0; h < 2; h++) {
                    float* a = acc[mt * 4 + np * 2 + h];
                    int m = m0 + wm * 32 + mt * 16 + row0;
                    int c = wn * 32 + np * 16 + h * 8 + col0;
                    float b0 = bias[c], b1v = bias[c + 1];
                    float v0 = a[0] + b0, v1 = a[1] + b1v;
                    float v2 = a[2] + b0, v3 = a[3] + b1v;
                    v0 = (v0 > 0.f) ? v0 : expm1f(v0);
                    v1 = (v1 > 0.f) ? v1 : expm1f(v1);
                    v2 = (v2 > 0.f) ? v2 : expm1f(v2);
                    v3 = (v3 > 0.f) ? v3 : expm1f(v3);
                    *(float2*)&xnext[(size_t)m * CO + c] = make_float2(v0, v1);
                    *(float2*)&xnext[(size_t)(m + 8) * CO + c] = make_float2(v2, v3);
                }
            }
        }
    }
}

// ---------------- pooling ----------------
__global__ void k_pool1(const float* __restrict__ x3, const int* __restrict__ n2s) {
    int idx = blockIdx.x * blockDim.x + threadIdx.x;
    if (idx >= N_NODES * 64) return;
    int n = idx / 64, o = idx % 64;
    int s = n2s[n];
    atomicAdd(&g_sub[s * 64 + o], x3[idx]);
    if (o == 0) atomicAdd(&g_subcnt[s], 1.f);
}

__global__ void k_pool2(const int* __restrict__ s2g) {
    int idx = blockIdx.x * blockDim.x + threadIdx.x;
    if (idx >= N_SUB * 64) return;
    int s = idx / 64, o = idx % 64;
    float m = g_sub[idx] / fmaxf(g_subcnt[s], 1.f);
    int g = s2g[s];
    atomicAdd(&g_graph[g * 64 + o], m);
    if (o == 0) atomicAdd(&g_graphcnt[g], 1.f);
}

// ---------------- final MLP (single block) ----------------
__global__ void k_fc(const float* __restrict__ fc1w, const float* __restrict__ fc1b,
                     const float* __restrict__ fc2w, const float* __restrict__ fc2b,
                     const float* __restrict__ fc3w, const float* __restrict__ fc3b,
                     float* __restrict__ out)
{
    __shared__ float hg[32 * 64];
    __shared__ float h1[32 * 32];
    __shared__ float h2[32 * 16];
    int t = threadIdx.x;  // 256
    for (int idx = t; idx < 32 * 64; idx += 256) {
        int g = idx / 64;
        hg[idx] = g_graph[idx] / fmaxf(g_graphcnt[g], 1.f);
    }
    __syncthreads();
    for (int idx = t; idx < 32 * 32; idx += 256) {
        int g = idx / 32, o = idx % 32;
        float v = fc1b[o];
        for (int i = 0; i < 64; i++) v += hg[g * 64 + i] * fc1w[i * 32 + o];
        h1[idx] = (v > 0.f) ? v : expm1f(v);
    }
    __syncthreads();
    for (int idx = t; idx < 32 * 16; idx += 256) {
        int g = idx / 16, o = idx % 16;
        float v = fc2b[o];
        for (int i = 0; i < 32; i++) v += h1[g * 32 + i] * fc2w[i * 16 + o];
        h2[idx] = (v > 0.f) ? v : expm1f(v);
    }
    __syncthreads();
    if (t < 32) {
        float v = fc3b[0];
        for (int i = 0; i < 16; i++) v += h2[t * 16 + i] * fc3w[i];
        out[t] = v;
    }
}

// ---------------- host launch ----------------
extern "C" void kernel_launch(void* const* d_in, const int* in_sizes, int n_in,
                              void* d_out, int out_size)
{
    const float* x     = (const float*)d_in[0];
    const int*   ei    = (const int*)d_in[1];
    const float* eattr = (const float*)d_in[2];
    const int*   n2s   = (const int*)d_in[3];
    const int*   s2g   = (const int*)d_in[4];
    const float* W1[3]   = {(const float*)d_in[5],  (const float*)d_in[11], (const float*)d_in[17]};
    const float* b1[3]   = {(const float*)d_in[6],  (const float*)d_in[12], (const float*)d_in[18]};
    const float* W2[3]   = {(const float*)d_in[7],  (const float*)d_in[13], (const float*)d_in[19]};
    const float* b2[3]   = {(const float*)d_in[8],  (const float*)d_in[14], (const float*)d_in[20]};
    const float* root[3] = {(const float*)d_in[9],  (const float*)d_in[15], (const float*)d_in[21]};
    const float* bias[3] = {(const float*)d_in[10], (const float*)d_in[16], (const float*)d_in[22]};
    const float* fc1w = (const float*)d_in[23];
    const float* fc1b = (const float*)d_in[24];
    const float* fc2w = (const float*)d_in[25];
    const float* fc2b = (const float*)d_in[26];
    const float* fc3w = (const float*)d_in[27];
    const float* fc3b = (const float*)d_in[28];
    float* out = (float*)d_out;

    float *xa, *xb;
    cudaGetSymbolAddress((void**)&xa, g_xa);
    cudaGetSymbolAddress((void**)&xb, g_xb);

    // dynamic smem: 4 stages. CO=64: 4*18432=73728B; CO=32: 4*14336=57344B
    static bool attr_set = false;
    if (!attr_set) {
        cudaFuncSetAttribute(k_gemm64, cudaFuncAttributeMaxDynamicSharedMemorySize, 73728);
        cudaFuncSetAttribute(k_gemm32, cudaFuncAttributeMaxDynamicSharedMemorySize, 57344);
        attr_set = true;
    }

    // prologue: fused init+bsplit, then CSR build
    k_init_bsplit<<<(BTOT + 255) / 256, 256>>>(W2[0], b2[0], root[0],
                                               W2[1], b2[1], root[1],
                                               W2[2], b2[2], root[2]);
    k_count<<<N_EDGES / 256, 256>>>(ei);
    k_scan<<<1, 1024>>>();
    k_fill<<<N_EDGES / 256, 256>>>(ei);

    const int KP[3] = {KP0, KP1, KP2};
    const int BOFF[3] = {BOFF0, BOFF1, BOFF2};
    const float* xcur = x;
    float* xnext = xa;

    for (int l = 0; l < 3; l++) {
        const int sgrid = N_NODES / NODES_PER_BLK;
        if (l == 0)      k_scatter<16><<<sgrid, 128>>>(xcur, ei, eattr, W1[l], b1[l], KP[l]);
        else if (l == 1) k_scatter<32><<<sgrid, 128>>>(xcur, ei, eattr, W1[l], b1[l], KP[l]);
        else             k_scatter<64><<<sgrid, 128>>>(xcur, ei, eattr, W1[l], b1[l], KP[l]);

        if (l == 0)
            k_gemm32<<<N_NODES / 64, 256, 57344>>>(KP[l], BOFF[l], xnext, bias[l]);
        else
            k_gemm64<<<N_NODES / 64, 256, 73728>>>(KP[l], BOFF[l], xnext, bias[l]);

        xcur = xnext;
        xnext = (xnext == xa) ? xb : xa;
    }

    // pooling + MLP head
    k_pool1<<<(N_NODES * 64 + 255) / 256, 256>>>(xcur, n2s);
    k_pool2<<<(N_SUB * 64 + 255) / 256, 256>>>(s2g);
    k_fc<<<1, 256>>>(fc1w, fc1b, fc2w, fc2b, fc3w, fc3b, out);
}

// round 15
// speedup vs baseline: 1.2633x; 1.0433x over previous
#include <cuda_runtime.h>
#include <cuda_fp16.h>
#include <cstdint>

#define N_NODES 8192
#define N_EDGES 32768
#define HID 128
#define N_SUB 512
#define N_GRAPH 32

// K' per layer (K + 2*ci, padded to multiple of 64)
#define KP0 2112
#define KP1 4160
#define KP2 8320
// B' buffer offsets (elems)
#define BOFF0 0
#define BOFF1 67584            // 2112*32
#define BOFF2 333824           // 67584 + 4160*64
#define BTOT  866304           // 333824 + 8320*64

// ---------------- device scratch (static; no allocations) ----------------
__device__ __half g_S[8192ull * 8320];   // [n][K'] fp16
__device__ __half g_Bh[BTOT];            // [K'][co] fp16, k-major
__device__ float g_xa[N_NODES * 64];
__device__ float g_xb[N_NODES * 64];
__device__ int   g_rowptr[N_NODES + 1];
__device__ int   g_fill[N_NODES];
__device__ int   g_eperm[N_EDGES];
__device__ float g_sub[N_SUB * 64];
__device__ float g_subcnt[N_SUB];
__device__ float g_graph[N_GRAPH * 64];
__device__ float g_graphcnt[N_GRAPH];

// ---------------- PTX helpers (baseline ISA only; no arch-suffix gating) --------
__device__ __forceinline__ uint32_t smem_u32(const void* p) {
    uint32_t a;
    asm("{ .reg .u64 t; cvta.to.shared.u64 t, %1; cvt.u32.u64 %0, t; }" : "=r"(a) : "l"(p));
    return a;
}
__device__ __forceinline__ void ldsm_x4(uint32_t& r0, uint32_t& r1, uint32_t& r2,
                                        uint32_t& r3, uint32_t addr) {
    asm volatile("ldmatrix.sync.aligned.m8n8.x4.shared.b16 {%0,%1,%2,%3}, [%4];"
                 : "=r"(r0), "=r"(r1), "=r"(r2), "=r"(r3) : "r"(addr));
}
__device__ __forceinline__ void ldsm_x4t(uint32_t& r0, uint32_t& r1, uint32_t& r2,
                                         uint32_t& r3, uint32_t addr) {
    asm volatile("ldmatrix.sync.aligned.m8n8.x4.trans.shared.b16 {%0,%1,%2,%3}, [%4];"
                 : "=r"(r0), "=r"(r1), "=r"(r2), "=r"(r3) : "r"(addr));
}
__device__ __forceinline__ void mma_f16(float& d0, float& d1, float& d2, float& d3,
                                        uint32_t a0, uint32_t a1, uint32_t a2, uint32_t a3,
                                        uint32_t b0, uint32_t b1) {
    asm volatile(
        "mma.sync.aligned.m16n8k16.row.col.f32.f16.f16.f32 "
        "{%0,%1,%2,%3}, {%4,%5,%6,%7}, {%8,%9}, {%0,%1,%2,%3};"
        : "+f"(d0), "+f"(d1), "+f"(d2), "+f"(d3)
        : "r"(a0), "r"(a1), "r"(a2), "r"(a3), "r"(b0), "r"(b1));
}
#define CP_ASYNC16(dst, src) \
    asm volatile("cp.async.cg.shared.global [%0], [%1], 16;" :: "r"(dst), "l"(src))
#define CP_COMMIT() asm volatile("cp.async.commit_group;" ::: "memory")
#define CP_WAIT4()  asm volatile("cp.async.wait_group 4;" ::: "memory")

// ---------------- init + B' conversion fused (both pure writers) ----------------
__global__ void k_init_bsplit(
    const float* __restrict__ W2_0, const float* __restrict__ b2_0, const float* __restrict__ rt_0,
    const float* __restrict__ W2_1, const float* __restrict__ b2_1, const float* __restrict__ rt_1,
    const float* __restrict__ W2_2, const float* __restrict__ b2_2, const float* __restrict__ rt_2)
{
    int idx = blockIdx.x * blockDim.x + threadIdx.x;
    if (idx <= N_NODES) g_rowptr[idx] = 0;
    if (idx < N_SUB * 64)   g_sub[idx] = 0.f;
    if (idx < N_SUB)        g_subcnt[idx] = 0.f;
    if (idx < N_GRAPH * 64) g_graph[idx] = 0.f;
    if (idx < N_GRAPH)      g_graphcnt[idx] = 0.f;

    if (idx >= BTOT) return;
    int rel, ci, co, K;
    const float *W2, *b2, *rt;
    if (idx < BOFF1)      { rel = idx;         ci = 16; co = 32; K = 2048; W2 = W2_0; b2 = b2_0; rt = rt_0; }
    else if (idx < BOFF2) { rel = idx - BOFF1; ci = 32; co = 64; K = 4096; W2 = W2_1; b2 = b2_1; rt = rt_1; }
    else                  { rel = idx - BOFF2; ci = 64; co = 64; K = 8192; W2 = W2_2; b2 = b2_2; rt = rt_2; }
    int kk = rel / co, o = rel % co;
    float w;
    if (kk < K) {
        int i = kk >> 7, k = kk & 127;
        w = W2[(k * ci + i) * co + o];
    } else if (kk < K + ci) {
        w = b2[(kk - K) * co + o];
    } else if (kk < K + 2 * ci) {
        w = rt[(kk - K - ci) * co + o];
    } else {
        w = 0.f;
    }
    g_Bh[idx] = __float2half_rn(w);
}

__global__ void k_count(const int* __restrict__ ei) {
    int e = blockIdx.x * blockDim.x + threadIdx.x;
    if (e < N_EDGES) atomicAdd(&g_rowptr[ei[N_EDGES + e] + 1], 1);
}

__global__ void k_scan() {
    __shared__ int part[1024];
    int t = threadIdx.x;
    int v[8];
    int run = 0;
#pragma unroll
    for (int q = 0; q < 8; q++) { run += g_rowptr[1 + t * 8 + q]; v[q] = run; }
    part[t] = run;
    __syncthreads();
    int sum = run;
    for (int off = 1; off < 1024; off <<= 1) {
        int other = (t >= off) ? part[t - off] : 0;
        __syncthreads();
        sum += other;
        part[t] = sum;
        __syncthreads();
    }
    int add = sum - run;
#pragma unroll
    for (int q = 0; q < 8; q++) {
        int val = v[q] + add;
        int pos = 1 + t * 8 + q;
        g_rowptr[pos] = val;
        if (pos < N_NODES) g_fill[pos] = val;
    }
    if (t == 0) { g_rowptr[0] = 0; g_fill[0] = 0; }
}

__global__ void k_fill(const int* __restrict__ ei) {
    int e = blockIdx.x * blockDim.x + threadIdx.x;
    if (e < N_EDGES) {
        int d = ei[N_EDGES + e];
        int pos = atomicAdd(&g_fill[d], 1);
        g_eperm[pos] = e;
    }
}

// ---------------- scatter (R12 form): S'[n] = [S | xs | x | 0pad] as fp16 -------
template <int CI>
__global__ __launch_bounds__(128) void k_scatter(
    const float* __restrict__ xcur, const int* __restrict__ ei,
    const float* __restrict__ eattr, const float* __restrict__ W1,
    const float* __restrict__ b1, int KP)
{
    constexpr int K = CI * 128;
    int n = blockIdx.x;
    int t = threadIdx.x;
    int w = t >> 5, lane = t & 31;
    __shared__ float sx[4][CI];
    __shared__ float sattr[4][5];

    float w1r[5];
#pragma unroll
    for (int j = 0; j < 5; j++) w1r[j] = W1[j * HID + t];
    float b1r = b1[t];

    float sacc[CI];
#pragma unroll
    for (int i = 0; i < CI; i++) sacc[i] = 0.f;
    float xsacc = 0.f;

    int beg = g_rowptr[n], end = g_rowptr[n + 1];
    for (int j0 = beg; j0 < end; j0 += 4) {
        int cnt = min(4, end - j0);
        if (w < cnt) {
            int e = g_eperm[j0 + w];
            int src = ei[e];
            if (lane < 5) sattr[w][lane] = eattr[e * 5 + lane];
#pragma unroll
            for (int i = lane; i < CI; i += 32) sx[w][i] = xcur[src * CI + i];
        }
        __syncthreads();
        for (int c = 0; c < cnt; c++) {
            float h = b1r;
#pragma unroll
            for (int q = 0; q < 5; q++) h += sattr[c][q] * w1r[q];
            h = fmaxf(h, 0.f);
#pragma unroll
            for (int i = 0; i < CI; i++) sacc[i] += h * sx[c][i];
            if (t < CI) xsacc += sx[c][t];
        }
        __syncthreads();
    }

    size_t base = (size_t)n * KP;
#pragma unroll
    for (int i = 0; i < CI; i++)
        g_S[base + (size_t)i * HID + t] = __float2half_rn(sacc[i]);
    int ext = KP - K;
    if (t < ext) {
        float v;
        if (t < CI) v = xsacc;
        else if (t < 2 * CI) v = xcur[n * CI + (t - CI)];
        else v = 0.f;
        g_S[base + K + t] = __float2half_rn(v);
    }
}

// ---------------- GEMM CO=32 (layer 1): fp16 single product, 6-stage ring ------
__global__ __launch_bounds__(256) void k_gemm32(int KP, int boff,
                                                float* __restrict__ xnext,
                                                const float* __restrict__ bias)
{
    constexpr int CO = 32;
    constexpr int AP = 72;
    constexpr int BP = CO + 8;                 // 40
    constexpr uint32_t A_OFF = 0;
    constexpr uint32_t BH_OFF = 64 * AP * 2;   // 9216
    constexpr uint32_t STAGE = BH_OFF + 64 * BP * 2;    // 14336
    constexpr int NSTAGE = 6;

    extern __shared__ char smem[];
    const uint32_t sb = smem_u32(smem);

    const int t = threadIdx.x;
    const int wid = t >> 5, lane = t & 31;
    const int wm = wid & 3;
    const int wn = wid >> 2;
    const int m0 = blockIdx.x * 64;

    float acc[2][4];
#pragma unroll
    for (int i = 0; i < 2; i++)
#pragma unroll
        for (int j = 0; j < 4; j++) acc[i][j] = 0.f;

    const int nIter = KP / 64;   // >= 33 always

    auto issue = [&](int sg, int kt) {
        uint32_t s0 = sb + sg * STAGE;
#pragma unroll
        for (int p = 0; p < 2; p++) {
            int c = t + 256 * p;
            int row = c >> 3, cc = c & 7;
            uint32_t d = s0 + (uint32_t)(row * AP + cc * 8) * 2u;
            CP_ASYNC16(d + A_OFF, &g_S[(size_t)(m0 + row) * KP + kt + cc * 8]);
        }
        {
            int c = t;
            int row = c >> 2, cc = c & 3;
            uint32_t d = s0 + (uint32_t)(row * BP + cc * 8) * 2u;
            CP_ASYNC16(d + BH_OFF, &g_Bh[boff + (size_t)(kt + row) * CO + cc * 8]);
        }
    };

#pragma unroll
    for (int s = 0; s < NSTAGE - 1; s++) { issue(s, s * 64); CP_COMMIT(); }

    for (int it = 0; it < nIter; it++) {
        CP_WAIT4();
        __syncthreads();
        if (it + NSTAGE - 1 < nIter) {
            int sg = (it + NSTAGE - 1) % NSTAGE;
            issue(sg, (it + NSTAGE - 1) * 64);
        }
        CP_COMMIT();

        uint32_t s0 = sb + (it % NSTAGE) * STAGE;
#pragma unroll
        for (int ks = 0; ks < 4; ks++) {
            uint32_t a_off = s0 + (uint32_t)((wm * 16 + (lane & 15)) * AP +
                                             ks * 16 + (lane >> 4) * 8) * 2u;
            uint32_t a0, a1, a2, a3;
            ldsm_x4(a0, a1, a2, a3, a_off + A_OFF);
            {
                int nb = wn * 16;
                uint32_t b_off = s0 + (uint32_t)((ks * 16 + (lane & 15)) * BP +
                                                 nb + (lane >> 4) * 8) * 2u;
                uint32_t bh0, bh1, bh2, bh3;
                ldsm_x4t(bh0, bh1, bh2, bh3, b_off + BH_OFF);
                mma_f16(acc[0][0], acc[0][1], acc[0][2], acc[0][3], a0, a1, a2, a3, bh0, bh1);
                mma_f16(acc[1][0], acc[1][1], acc[1][2], acc[1][3], a0, a1, a2, a3, bh2, bh3);
            }
        }
    }

    const int row0 = lane >> 2;
    const int col0 = (lane & 3) * 2;
#pragma unroll
    for (int nt = 0; nt < 2; nt++) {
        int m = m0 + wm * 16 + row0;
        int c = wn * 16 + nt * 8 + col0;
        float b0 = bias[c], b1v = bias[c + 1];
        float v0 = acc[nt][0] + b0, v1 = acc[nt][1] + b1v;
        float v2 = acc[nt][2] + b0, v3 = acc[nt][3] + b1v;
        v0 = (v0 > 0.f) ? v0 : expm1f(v0);
        v1 = (v1 > 0.f) ? v1 : expm1f(v1);
        v2 = (v2 > 0.f) ? v2 : expm1f(v2);
        v3 = (v3 > 0.f) ? v3 : expm1f(v3);
        *(float2*)&xnext[(size_t)m * CO + c] = make_float2(v0, v1);
        *(float2*)&xnext[(size_t)(m + 8) * CO + c] = make_float2(v2, v3);
    }
}

// ---------------- GEMM CO=64: m32n32 warp tile, 2-way split-K, 6-stage ring ----
__global__ __launch_bounds__(256) void k_gemm64(int KP, int boff,
                                                float* __restrict__ xnext,
                                                const float* __restrict__ bias)
{
    constexpr int CO = 64;
    constexpr int AP = 72;
    constexpr int BP = CO + 8;                 // 72
    constexpr uint32_t A_OFF = 0;
    constexpr uint32_t BH_OFF = 64 * AP * 2;   // 9216
    constexpr uint32_t STAGE = BH_OFF + 64 * BP * 2;    // 18432
    constexpr int NSTAGE = 6;

    extern __shared__ char smem[];
    const uint32_t sb = smem_u32(smem);

    const int t = threadIdx.x;
    const int wid = t >> 5, lane = t & 31;
    const int wk = wid >> 2;
    const int wm = (wid >> 1) & 1;
    const int wn = wid & 1;
    const int m0 = blockIdx.x * 64;

    float acc[8][4];
#pragma unroll
    for (int i = 0; i < 8; i++)
#pragma unroll
        for (int j = 0; j < 4; j++) acc[i][j] = 0.f;

    const int nIter = KP / 64;

    auto issue = [&](int sg, int kt) {
        uint32_t s0 = sb + sg * STAGE;
#pragma unroll
        for (int p = 0; p < 2; p++) {
            int c = t + 256 * p;
            int row = c >> 3, cc = c & 7;
            uint32_t d = s0 + (uint32_t)(row * AP + cc * 8) * 2u;
            CP_ASYNC16(d + A_OFF, &g_S[(size_t)(m0 + row) * KP + kt + cc * 8]);
        }
#pragma unroll
        for (int p = 0; p < 2; p++) {
            int c = t + 256 * p;
            int row = c >> 3, cc = c & 7;
            uint32_t d = s0 + (uint32_t)(row * BP + cc * 8) * 2u;
            CP_ASYNC16(d + BH_OFF, &g_Bh[boff + (size_t)(kt + row) * CO + cc * 8]);
        }
    };

#pragma unroll
    for (int s = 0; s < NSTAGE - 1; s++) { issue(s, s * 64); CP_COMMIT(); }

    for (int it = 0; it < nIter; it++) {
        CP_WAIT4();
        __syncthreads();
        if (it + NSTAGE - 1 < nIter) {
            int sg = (it + NSTAGE - 1) % NSTAGE;
            issue(sg, (it + NSTAGE - 1) * 64);
        }
        CP_COMMIT();

        uint32_t s0 = sb + (it % NSTAGE) * STAGE;
#pragma unroll
        for (int ks2 = 0; ks2 < 2; ks2++) {
            int kk = wk * 32 + ks2 * 16;
            uint32_t ah[2][4];
#pragma unroll
            for (int mt = 0; mt < 2; mt++) {
                uint32_t a_off = s0 + (uint32_t)((wm * 32 + mt * 16 + (lane & 15)) * AP +
                                                 kk + (lane >> 4) * 8) * 2u;
                ldsm_x4(ah[mt][0], ah[mt][1], ah[mt][2], ah[mt][3], a_off + A_OFF);
            }
            uint32_t bh[2][4];
#pragma unroll
            for (int np = 0; np < 2; np++) {
                int nb = wn * 32 + np * 16;
                uint32_t b_off = s0 + (uint32_t)((kk + (lane & 15)) * BP +
                                                 nb + (lane >> 4) * 8) * 2u;
                ldsm_x4t(bh[np][0], bh[np][1], bh[np][2], bh[np][3], b_off + BH_OFF);
            }
#pragma unroll
            for (int mt = 0; mt < 2; mt++) {
#pragma unroll
                for (int np = 0; np < 2; np++) {
                    float* c0 = acc[mt * 4 + np * 2 + 0];
                    float* c1 = acc[mt * 4 + np * 2 + 1];
                    mma_f16(c0[0], c0[1], c0[2], c0[3],
                            ah[mt][0], ah[mt][1], ah[mt][2], ah[mt][3], bh[np][0], bh[np][1]);
                    mma_f16(c1[0], c1[1], c1[2], c1[3],
                            ah[mt][0], ah[mt][1], ah[mt][2], ah[mt][3], bh[np][2], bh[np][3]);
                }
            }
        }
    }

    // ---- split-K reduction: wk=1 warps dump acc to smem, wk=0 warps add ----
    __syncthreads();
    {
        float* red = (float*)smem;
        int pair = wm * 2 + wn;
        if (wk == 1) {
#pragma unroll
            for (int j = 0; j < 8; j++)
#pragma unroll
                for (int q = 0; q < 4; q++)
                    red[pair * 1024 + (j * 4 + q) * 32 + lane] = acc[j][q];
        }
        __syncthreads();
        if (wk == 0) {
#pragma unroll
            for (int j = 0; j < 8; j++)
#pragma unroll
                for (int q = 0; q < 4; q++)
                    acc[j][q] += red[pair * 1024 + (j * 4 + q) * 32 + lane];
        }
    }

    if (wk == 0) {
        const int row0 = lane >> 2;
        const int col0 = (lane & 3) * 2;
#pragma unroll
        for (int mt = 0; mt < 2; mt++) {
#pragma unroll
            for (int np = 0; np < 2; np++) {
#pragma unroll
                for (int h = 0; h < 2; h++) {
                    float* a = acc[mt * 4 + np * 2 + h];
                    int m = m0 + wm * 32 + mt * 16 + row0;
                    int c = wn * 32 + np * 16 + h * 8 + col0;
                    float b0 = bias[c], b1v = bias[c + 1];
                    float v0 = a[0] + b0, v1 = a[1] + b1v;
                    float v2 = a[2] + b0, v3 = a[3] + b1v;
                    v0 = (v0 > 0.f) ? v0 : expm1f(v0);
                    v1 = (v1 > 0.f) ? v1 : expm1f(v1);
                    v2 = (v2 > 0.f) ? v2 : expm1f(v2);
                    v3 = (v3 > 0.f) ? v3 : expm1f(v3);
                    *(float2*)&xnext[(size_t)m * CO + c] = make_float2(v0, v1);
                    *(float2*)&xnext[(size_t)(m + 8) * CO + c] = make_float2(v2, v3);
                }
            }
        }
    }
}

// ---------------- pooling ----------------
__global__ void k_pool1(const float* __restrict__ x3, const int* __restrict__ n2s) {
    int idx = blockIdx.x * blockDim.x + threadIdx.x;
    if (idx >= N_NODES * 64) return;
    int n = idx / 64, o = idx % 64;
    int s = n2s[n];
    atomicAdd(&g_sub[s * 64 + o], x3[idx]);
    if (o == 0) atomicAdd(&g_subcnt[s], 1.f);
}

__global__ void k_pool2(const int* __restrict__ s2g) {
    int idx = blockIdx.x * blockDim.x + threadIdx.x;
    if (idx >= N_SUB * 64) return;
    int s = idx / 64, o = idx % 64;
    float m = g_sub[idx] / fmaxf(g_subcnt[s], 1.f);
    int g = s2g[s];
    atomicAdd(&g_graph[g * 64 + o], m);
    if (o == 0) atomicAdd(&g_graphcnt[g], 1.f);
}

// ---------------- final MLP (single block) ----------------
__global__ void k_fc(const float* __restrict__ fc1w, const float* __restrict__ fc1b,
                     const float* __restrict__ fc2w, const float* __restrict__ fc2b,
                     const float* __restrict__ fc3w, const float* __restrict__ fc3b,
                     float* __restrict__ out)
{
    __shared__ float hg[32 * 64];
    __shared__ float h1[32 * 32];
    __shared__ float h2[32 * 16];
    int t = threadIdx.x;  // 256
    for (int idx = t; idx < 32 * 64; idx += 256) {
        int g = idx / 64;
        hg[idx] = g_graph[idx] / fmaxf(g_graphcnt[g], 1.f);
    }
    __syncthreads();
    for (int idx = t; idx < 32 * 32; idx += 256) {
        int g = idx / 32, o = idx % 32;
        float v = fc1b[o];
        for (int i = 0; i < 64; i++) v += hg[g * 64 + i] * fc1w[i * 32 + o];
        h1[idx] = (v > 0.f) ? v : expm1f(v);
    }
    __syncthreads();
    for (int idx = t; idx < 32 * 16; idx += 256) {
        int g = idx / 16, o = idx % 16;
        float v = fc2b[o];
        for (int i = 0; i < 32; i++) v += h1[g * 32 + i] * fc2w[i * 16 + o];
        h2[idx] = (v > 0.f) ? v : expm1f(v);
    }
    __syncthreads();
    if (t < 32) {
        float v = fc3b[0];
        for (int i = 0; i < 16; i++) v += h2[t * 16 + i] * fc3w[i];
        out[t] = v;
    }
}

// ---------------- host launch ----------------
extern "C" void kernel_launch(void* const* d_in, const int* in_sizes, int n_in,
                              void* d_out, int out_size)
{
    const float* x     = (const float*)d_in[0];
    const int*   ei    = (const int*)d_in[1];
    const float* eattr = (const float*)d_in[2];
    const int*   n2s   = (const int*)d_in[3];
    const int*   s2g   = (const int*)d_in[4];
    const float* W1[3]   = {(const float*)d_in[5],  (const float*)d_in[11], (const float*)d_in[17]};
    const float* b1[3]   = {(const float*)d_in[6],  (const float*)d_in[12], (const float*)d_in[18]};
    const float* W2[3]   = {(const float*)d_in[7],  (const float*)d_in[13], (const float*)d_in[19]};
    const float* b2[3]   = {(const float*)d_in[8],  (const float*)d_in[14], (const float*)d_in[20]};
    const float* root[3] = {(const float*)d_in[9],  (const float*)d_in[15], (const float*)d_in[21]};
    const float* bias[3] = {(const float*)d_in[10], (const float*)d_in[16], (const float*)d_in[22]};
    const float* fc1w = (const float*)d_in[23];
    const float* fc1b = (const float*)d_in[24];
    const float* fc2w = (const float*)d_in[25];
    const float* fc2b = (const float*)d_in[26];
    const float* fc3w = (const float*)d_in[27];
    const float* fc3b = (const float*)d_in[28];
    float* out = (float*)d_out;

    float *xa, *xb;
    cudaGetSymbolAddress((void**)&xa, g_xa);
    cudaGetSymbolAddress((void**)&xb, g_xb);

    // dynamic smem: 6 stages. CO=64: 6*18432=110592B; CO=32: 6*14336=86016B
    static bool attr_set = false;
    if (!attr_set) {
        cudaFuncSetAttribute(k_gemm64, cudaFuncAttributeMaxDynamicSharedMemorySize, 110592);
        cudaFuncSetAttribute(k_gemm32, cudaFuncAttributeMaxDynamicSharedMemorySize, 86016);
        attr_set = true;
    }

    // prologue: fused init+bsplit, then CSR build
    k_init_bsplit<<<(BTOT + 255) / 256, 256>>>(W2[0], b2[0], root[0],
                                               W2[1], b2[1], root[1],
                                               W2[2], b2[2], root[2]);
    k_count<<<N_EDGES / 256, 256>>>(ei);
    k_scan<<<1, 1024>>>();
    k_fill<<<N_EDGES / 256, 256>>>(ei);

    const int KP[3] = {KP0, KP1, KP2};
    const int BOFF[3] = {BOFF0, BOFF1, BOFF2};
    const float* xcur = x;
    float* xnext = xa;

    for (int l = 0; l < 3; l++) {
        if (l == 0)      k_scatter<16><<<N_NODES, 128>>>(xcur, ei, eattr, W1[l], b1[l], KP[l]);
        else if (l == 1) k_scatter<32><<<N_NODES, 128>>>(xcur, ei, eattr, W1[l], b1[l], KP[l]);
        else             k_scatter<64><<<N_NODES, 128>>>(xcur, ei, eattr, W1[l], b1[l], KP[l]);

        if (l == 0)
            k_gemm32<<<N_NODES / 64, 256, 86016>>>(KP[l], BOFF[l], xnext, bias[l]);
        else
            k_gemm64<<<N_NODES / 64, 256, 110592>>>(KP[l], BOFF[l], xnext, bias[l]);

        xcur = xnext;
        xnext = (xnext == xa) ? xb : xa;
    }

    // pooling + MLP head
    k_pool1<<<(N_NODES * 64 + 255) / 256, 256>>>(xcur, n2s);
    k_pool2<<<(N_SUB * 64 + 255) / 256, 256>>>(s2g);
    k_fc<<<1, 256>>>(fc1w, fc1b, fc2w, fc2b, fc3w, fc3b, out);
}

// round 16
// speedup vs baseline: 1.2648x; 1.0012x over previous
#include <cuda_runtime.h>
#include <cuda_fp16.h>
#include <cstdint>

#define N_NODES 8192
#define N_EDGES 32768
#define HID 128
#define N_SUB 512
#define N_GRAPH 32

// K' per layer (K + 2*ci, padded to multiple of 64)
#define KP0 2112
#define KP1 4160
#define KP2 8320
// B' buffer offsets (elems)
#define BOFF0 0
#define BOFF1 67584            // 2112*32
#define BOFF2 333824           // 67584 + 4160*64
#define BTOT  866304           // 333824 + 8320*64

// ---------------- device scratch (static; no allocations) ----------------
__device__ __half g_S[8192ull * 8320];   // [n][K'] fp16
__device__ __half g_Bh[BTOT];            // [K'][co] fp16, k-major
__device__ float g_xa[N_NODES * 64];
__device__ float g_xb[N_NODES * 64];
__device__ int   g_rowptr[N_NODES + 1];
__device__ int   g_fill[N_NODES];
__device__ int   g_eperm[N_EDGES];
__device__ float g_sub[N_SUB * 64];
__device__ float g_subcnt[N_SUB];
__device__ float g_graph[N_GRAPH * 64];
__device__ float g_graphcnt[N_GRAPH];

// ---------------- PTX helpers (baseline ISA only; no arch-suffix gating) --------
__device__ __forceinline__ uint32_t smem_u32(const void* p) {
    uint32_t a;
    asm("{ .reg .u64 t; cvta.to.shared.u64 t, %1; cvt.u32.u64 %0, t; }" : "=r"(a) : "l"(p));
    return a;
}
__device__ __forceinline__ void ldsm_x4(uint32_t& r0, uint32_t& r1, uint32_t& r2,
                                        uint32_t& r3, uint32_t addr) {
    asm volatile("ldmatrix.sync.aligned.m8n8.x4.shared.b16 {%0,%1,%2,%3}, [%4];"
                 : "=r"(r0), "=r"(r1), "=r"(r2), "=r"(r3) : "r"(addr));
}
__device__ __forceinline__ void ldsm_x4t(uint32_t& r0, uint32_t& r1, uint32_t& r2,
                                         uint32_t& r3, uint32_t addr) {
    asm volatile("ldmatrix.sync.aligned.m8n8.x4.trans.shared.b16 {%0,%1,%2,%3}, [%4];"
                 : "=r"(r0), "=r"(r1), "=r"(r2), "=r"(r3) : "r"(addr));
}
__device__ __forceinline__ void mma_f16(float& d0, float& d1, float& d2, float& d3,
                                        uint32_t a0, uint32_t a1, uint32_t a2, uint32_t a3,
                                        uint32_t b0, uint32_t b1) {
    asm volatile(
        "mma.sync.aligned.m16n8k16.row.col.f32.f16.f16.f32 "
        "{%0,%1,%2,%3}, {%4,%5,%6,%7}, {%8,%9}, {%0,%1,%2,%3};"
        : "+f"(d0), "+f"(d1), "+f"(d2), "+f"(d3)
        : "r"(a0), "r"(a1), "r"(a2), "r"(a3), "r"(b0), "r"(b1));
}
#define CP_ASYNC16(dst, src) \
    asm volatile("cp.async.cg.shared.global [%0], [%1], 16;" :: "r"(dst), "l"(src))
#define CP_COMMIT() asm volatile("cp.async.commit_group;" ::: "memory")
#define CP_WAIT2()  asm volatile("cp.async.wait_group 2;" ::: "memory")

// ---------------- init + B' conversion fused (both pure writers) ----------------
__global__ void k_init_bsplit(
    const float* __restrict__ W2_0, const float* __restrict__ b2_0, const float* __restrict__ rt_0,
    const float* __restrict__ W2_1, const float* __restrict__ b2_1, const float* __restrict__ rt_1,
    const float* __restrict__ W2_2, const float* __restrict__ b2_2, const float* __restrict__ rt_2)
{
    int idx = blockIdx.x * blockDim.x + threadIdx.x;
    if (idx <= N_NODES) g_rowptr[idx] = 0;
    if (idx < N_SUB * 64)   g_sub[idx] = 0.f;
    if (idx < N_SUB)        g_subcnt[idx] = 0.f;
    if (idx < N_GRAPH * 64) g_graph[idx] = 0.f;
    if (idx < N_GRAPH)      g_graphcnt[idx] = 0.f;

    if (idx >= BTOT) return;
    int rel, ci, co, K;
    const float *W2, *b2, *rt;
    if (idx < BOFF1)      { rel = idx;         ci = 16; co = 32; K = 2048; W2 = W2_0; b2 = b2_0; rt = rt_0; }
    else if (idx < BOFF2) { rel = idx - BOFF1; ci = 32; co = 64; K = 4096; W2 = W2_1; b2 = b2_1; rt = rt_1; }
    else                  { rel = idx - BOFF2; ci = 64; co = 64; K = 8192; W2 = W2_2; b2 = b2_2; rt = rt_2; }
    int kk = rel / co, o = rel % co;
    float w;
    if (kk < K) {
        int i = kk >> 7, k = kk & 127;
        w = W2[(k * ci + i) * co + o];
    } else if (kk < K + ci) {
        w = b2[(kk - K) * co + o];
    } else if (kk < K + 2 * ci) {
        w = rt[(kk - K - ci) * co + o];
    } else {
        w = 0.f;
    }
    g_Bh[idx] = __float2half_rn(w);
}

__global__ void k_count(const int* __restrict__ ei) {
    int e = blockIdx.x * blockDim.x + threadIdx.x;
    if (e < N_EDGES) atomicAdd(&g_rowptr[ei[N_EDGES + e] + 1], 1);
}

__global__ void k_scan() {
    __shared__ int part[1024];
    int t = threadIdx.x;
    int v[8];
    int run = 0;
#pragma unroll
    for (int q = 0; q < 8; q++) { run += g_rowptr[1 + t * 8 + q]; v[q] = run; }
    part[t] = run;
    __syncthreads();
    int sum = run;
    for (int off = 1; off < 1024; off <<= 1) {
        int other = (t >= off) ? part[t - off] : 0;
        __syncthreads();
        sum += other;
        part[t] = sum;
        __syncthreads();
    }
    int add = sum - run;
#pragma unroll
    for (int q = 0; q < 8; q++) {
        int val = v[q] + add;
        int pos = 1 + t * 8 + q;
        g_rowptr[pos] = val;
        if (pos < N_NODES) g_fill[pos] = val;
    }
    if (t == 0) { g_rowptr[0] = 0; g_fill[0] = 0; }
}

__global__ void k_fill(const int* __restrict__ ei) {
    int e = blockIdx.x * blockDim.x + threadIdx.x;
    if (e < N_EDGES) {
        int d = ei[N_EDGES + e];
        int pos = atomicAdd(&g_fill[d], 1);
        g_eperm[pos] = e;
    }
}

// ---------------- scatter: S'[n] = [S | xs | x | 0pad] as fp16 -------------------
// float4-vectorized smem reads: 1 LDS.128 per 4 FFMA (was 1 LDS per FFMA).
// Same accumulation order as R12 -> bit-identical results.
template <int CI>
__global__ __launch_bounds__(128) void k_scatter(
    const float* __restrict__ xcur, const int* __restrict__ ei,
    const float* __restrict__ eattr, const float* __restrict__ W1,
    const float* __restrict__ b1, int KP)
{
    constexpr int K = CI * 128;
    int n = blockIdx.x;
    int t = threadIdx.x;
    int w = t >> 5, lane = t & 31;
    __shared__ __align__(16) float sx[4][CI];
    __shared__ float sattr[4][5];

    float w1r[5];
#pragma unroll
    for (int j = 0; j < 5; j++) w1r[j] = W1[j * HID + t];
    float b1r = b1[t];

    float sacc[CI];
#pragma unroll
    for (int i = 0; i < CI; i++) sacc[i] = 0.f;
    float xsacc = 0.f;

    int beg = g_rowptr[n], end = g_rowptr[n + 1];
    for (int j0 = beg; j0 < end; j0 += 4) {
        int cnt = min(4, end - j0);
        if (w < cnt) {
            int e = g_eperm[j0 + w];
            int src = ei[e];
            if (lane < 5) sattr[w][lane] = eattr[e * 5 + lane];
#pragma unroll
            for (int i = lane; i < CI; i += 32) sx[w][i] = xcur[src * CI + i];
        }
        __syncthreads();
        for (int c = 0; c < cnt; c++) {
            float h = b1r;
#pragma unroll
            for (int q = 0; q < 5; q++) h += sattr[c][q] * w1r[q];
            h = fmaxf(h, 0.f);
            const float4* sx4 = (const float4*)sx[c];
#pragma unroll
            for (int i4 = 0; i4 < CI / 4; i4++) {
                float4 v = sx4[i4];
                sacc[i4 * 4 + 0] += h * v.x;
                sacc[i4 * 4 + 1] += h * v.y;
                sacc[i4 * 4 + 2] += h * v.z;
                sacc[i4 * 4 + 3] += h * v.w;
            }
            if (t < CI) xsacc += sx[c][t];
        }
        __syncthreads();
    }

    size_t base = (size_t)n * KP;
#pragma unroll
    for (int i = 0; i < CI; i++)
        g_S[base + (size_t)i * HID + t] = __float2half_rn(sacc[i]);
    int ext = KP - K;
    if (t < ext) {
        float v;
        if (t < CI) v = xsacc;
        else if (t < 2 * CI) v = xcur[n * CI + (t - CI)];
        else v = 0.f;
        g_S[base + K + t] = __float2half_rn(v);
    }
}

// ---------------- GEMM CO=32 (layer 1): fp16 single product, 4-stage ring ------
__global__ __launch_bounds__(256) void k_gemm32(int KP, int boff,
                                                float* __restrict__ xnext,
                                                const float* __restrict__ bias)
{
    constexpr int CO = 32;
    constexpr int AP = 72;
    constexpr int BP = CO + 8;                 // 40
    constexpr uint32_t A_OFF = 0;
    constexpr uint32_t BH_OFF = 64 * AP * 2;   // 9216
    constexpr uint32_t STAGE = BH_OFF + 64 * BP * 2;    // 14336
    constexpr int NSTAGE = 4;

    extern __shared__ char smem[];
    const uint32_t sb = smem_u32(smem);

    const int t = threadIdx.x;
    const int wid = t >> 5, lane = t & 31;
    const int wm = wid & 3;
    const int wn = wid >> 2;
    const int m0 = blockIdx.x * 64;

    float acc[2][4];
#pragma unroll
    for (int i = 0; i < 2; i++)
#pragma unroll
        for (int j = 0; j < 4; j++) acc[i][j] = 0.f;

    const int nIter = KP / 64;

    auto issue = [&](int sg, int kt) {
        uint32_t s0 = sb + sg * STAGE;
#pragma unroll
        for (int p = 0; p < 2; p++) {
            int c = t + 256 * p;
            int row = c >> 3, cc = c & 7;
            uint32_t d = s0 + (uint32_t)(row * AP + cc * 8) * 2u;
            CP_ASYNC16(d + A_OFF, &g_S[(size_t)(m0 + row) * KP + kt + cc * 8]);
        }
        {
            int c = t;
            int row = c >> 2, cc = c & 3;
            uint32_t d = s0 + (uint32_t)(row * BP + cc * 8) * 2u;
            CP_ASYNC16(d + BH_OFF, &g_Bh[boff + (size_t)(kt + row) * CO + cc * 8]);
        }
    };

#pragma unroll
    for (int s = 0; s < NSTAGE - 1; s++) { issue(s, s * 64); CP_COMMIT(); }

    for (int it = 0; it < nIter; it++) {
        CP_WAIT2();
        __syncthreads();
        if (it + NSTAGE - 1 < nIter) issue((it + NSTAGE - 1) & (NSTAGE - 1),
                                           (it + NSTAGE - 1) * 64);
        CP_COMMIT();

        uint32_t s0 = sb + (it & (NSTAGE - 1)) * STAGE;
#pragma unroll
        for (int ks = 0; ks < 4; ks++) {
            uint32_t a_off = s0 + (uint32_t)((wm * 16 + (lane & 15)) * AP +
                                             ks * 16 + (lane >> 4) * 8) * 2u;
            uint32_t a0, a1, a2, a3;
            ldsm_x4(a0, a1, a2, a3, a_off + A_OFF);
            {
                int nb = wn * 16;
                uint32_t b_off = s0 + (uint32_t)((ks * 16 + (lane & 15)) * BP +
                                                 nb + (lane >> 4) * 8) * 2u;
                uint32_t bh0, bh1, bh2, bh3;
                ldsm_x4t(bh0, bh1, bh2, bh3, b_off + BH_OFF);
                mma_f16(acc[0][0], acc[0][1], acc[0][2], acc[0][3], a0, a1, a2, a3, bh0, bh1);
                mma_f16(acc[1][0], acc[1][1], acc[1][2], acc[1][3], a0, a1, a2, a3, bh2, bh3);
            }
        }
    }

    const int row0 = lane >> 2;
    const int col0 = (lane & 3) * 2;
#pragma unroll
    for (int nt = 0; nt < 2; nt++) {
        int m = m0 + wm * 16 + row0;
        int c = wn * 16 + nt * 8 + col0;
        float b0 = bias[c], b1v = bias[c + 1];
        float v0 = acc[nt][0] + b0, v1 = acc[nt][1] + b1v;
        float v2 = acc[nt][2] + b0, v3 = acc[nt][3] + b1v;
        v0 = (v0 > 0.f) ? v0 : expm1f(v0);
        v1 = (v1 > 0.f) ? v1 : expm1f(v1);
        v2 = (v2 > 0.f) ? v2 : expm1f(v2);
        v3 = (v3 > 0.f) ? v3 : expm1f(v3);
        *(float2*)&xnext[(size_t)m * CO + c] = make_float2(v0, v1);
        *(float2*)&xnext[(size_t)(m + 8) * CO + c] = make_float2(v2, v3);
    }
}

// ---------------- GEMM CO=64: m32n32 warp tile, 2-way split-K, 4-stage ring ----
__global__ __launch_bounds__(256) void k_gemm64(int KP, int boff,
                                                float* __restrict__ xnext,
                                                const float* __restrict__ bias)
{
    constexpr int CO = 64;
    constexpr int AP = 72;
    constexpr int BP = CO + 8;                 // 72
    constexpr uint32_t A_OFF = 0;
    constexpr uint32_t BH_OFF = 64 * AP * 2;   // 9216
    constexpr uint32_t STAGE = BH_OFF + 64 * BP * 2;    // 18432
    constexpr int NSTAGE = 4;

    extern __shared__ char smem[];
    const uint32_t sb = smem_u32(smem);

    const int t = threadIdx.x;
    const int wid = t >> 5, lane = t & 31;
    const int wk = wid >> 2;
    const int wm = (wid >> 1) & 1;
    const int wn = wid & 1;
    const int m0 = blockIdx.x * 64;

    float acc[8][4];
#pragma unroll
    for (int i = 0; i < 8; i++)
#pragma unroll
        for (int j = 0; j < 4; j++) acc[i][j] = 0.f;

    const int nIter = KP / 64;

    auto issue = [&](int sg, int kt) {
        uint32_t s0 = sb + sg * STAGE;
#pragma unroll
        for (int p = 0; p < 2; p++) {
            int c = t + 256 * p;
            int row = c >> 3, cc = c & 7;
            uint32_t d = s0 + (uint32_t)(row * AP + cc * 8) * 2u;
            CP_ASYNC16(d + A_OFF, &g_S[(size_t)(m0 + row) * KP + kt + cc * 8]);
        }
#pragma unroll
        for (int p = 0; p < 2; p++) {
            int c = t + 256 * p;
            int row = c >> 3, cc = c & 7;
            uint32_t d = s0 + (uint32_t)(row * BP + cc * 8) * 2u;
            CP_ASYNC16(d + BH_OFF, &g_Bh[boff + (size_t)(kt + row) * CO + cc * 8]);
        }
    };

#pragma unroll
    for (int s = 0; s < NSTAGE - 1; s++) { issue(s, s * 64); CP_COMMIT(); }

    for (int it = 0; it < nIter; it++) {
        CP_WAIT2();
        __syncthreads();
        if (it + NSTAGE - 1 < nIter) issue((it + NSTAGE - 1) & (NSTAGE - 1),
                                           (it + NSTAGE - 1) * 64);
        CP_COMMIT();

        uint32_t s0 = sb + (it & (NSTAGE - 1)) * STAGE;
#pragma unroll
        for (int ks2 = 0; ks2 < 2; ks2++) {
            int kk = wk * 32 + ks2 * 16;
            uint32_t ah[2][4];
#pragma unroll
            for (int mt = 0; mt < 2; mt++) {
                uint32_t a_off = s0 + (uint32_t)((wm * 32 + mt * 16 + (lane & 15)) * AP +
                                                 kk + (lane >> 4) * 8) * 2u;
                ldsm_x4(ah[mt][0], ah[mt][1], ah[mt][2], ah[mt][3], a_off + A_OFF);
            }
            uint32_t bh[2][4];
#pragma unroll
            for (int np = 0; np < 2; np++) {
                int nb = wn * 32 + np * 16;
                uint32_t b_off = s0 + (uint32_t)((kk + (lane & 15)) * BP +
                                                 nb + (lane >> 4) * 8) * 2u;
                ldsm_x4t(bh[np][0], bh[np][1], bh[np][2], bh[np][3], b_off + BH_OFF);
            }
#pragma unroll
            for (int mt = 0; mt < 2; mt++) {
#pragma unroll
                for (int np = 0; np < 2; np++) {
                    float* c0 = acc[mt * 4 + np * 2 + 0];
                    float* c1 = acc[mt * 4 + np * 2 + 1];
                    mma_f16(c0[0], c0[1], c0[2], c0[3],
                            ah[mt][0], ah[mt][1], ah[mt][2], ah[mt][3], bh[np][0], bh[np][1]);
                    mma_f16(c1[0], c1[1], c1[2], c1[3],
                            ah[mt][0], ah[mt][1], ah[mt][2], ah[mt][3], bh[np][2], bh[np][3]);
                }
            }
        }
    }

    // ---- split-K reduction: wk=1 warps dump acc to smem, wk=0 warps add ----
    __syncthreads();
    {
        float* red = (float*)smem;
        int pair = wm * 2 + wn;
        if (wk == 1) {
#pragma unroll
            for (int j = 0; j < 8; j++)
#pragma unroll
                for (int q = 0; q < 4; q++)
                    red[pair * 1024 + (j * 4 + q) * 32 + lane] = acc[j][q];
        }
        __syncthreads();
        if (wk == 0) {
#pragma unroll
            for (int j = 0; j < 8; j++)
#pragma unroll
                for (int q = 0; q < 4; q++)
                    acc[j][q] += red[pair * 1024 + (j * 4 + q) * 32 + lane];
        }
    }

    if (wk == 0) {
        const int row0 = lane >> 2;
        const int col0 = (lane & 3) * 2;
#pragma unroll
        for (int mt = 0; mt < 2; mt++) {
#pragma unroll
            for (int np = 0; np < 2; np++) {
#pragma unroll
                for (int h = 0; h < 2; h++) {
                    float* a = acc[mt * 4 + np * 2 + h];
                    int m = m0 + wm * 32 + mt * 16 + row0;
                    int c = wn * 32 + np * 16 + h * 8 + col0;
                    float b0 = bias[c], b1v = bias[c + 1];
                    float v0 = a[0] + b0, v1 = a[1] + b1v;
                    float v2 = a[2] + b0, v3 = a[3] + b1v;
                    v0 = (v0 > 0.f) ? v0 : expm1f(v0);
                    v1 = (v1 > 0.f) ? v1 : expm1f(v1);
                    v2 = (v2 > 0.f) ? v2 : expm1f(v2);
                    v3 = (v3 > 0.f) ? v3 : expm1f(v3);
                    *(float2*)&xnext[(size_t)m * CO + c] = make_float2(v0, v1);
                    *(float2*)&xnext[(size_t)(m + 8) * CO + c] = make_float2(v2, v3);
                }
            }
        }
    }
}

// ---------------- pooling ----------------
__global__ void k_pool1(const float* __restrict__ x3, const int* __restrict__ n2s) {
    int idx = blockIdx.x * blockDim.x + threadIdx.x;
    if (idx >= N_NODES * 64) return;
    int n = idx / 64, o = idx % 64;
    int s = n2s[n];
    atomicAdd(&g_sub[s * 64 + o], x3[idx]);
    if (o == 0) atomicAdd(&g_subcnt[s], 1.f);
}

__global__ void k_pool2(const int* __restrict__ s2g) {
    int idx = blockIdx.x * blockDim.x + threadIdx.x;
    if (idx >= N_SUB * 64) return;
    int s = idx / 64, o = idx % 64;
    float m = g_sub[idx] / fmaxf(g_subcnt[s], 1.f);
    int g = s2g[s];
    atomicAdd(&g_graph[g * 64 + o], m);
    if (o == 0) atomicAdd(&g_graphcnt[g], 1.f);
}

// ---------------- final MLP (single block) ----------------
__global__ void k_fc(const float* __restrict__ fc1w, const float* __restrict__ fc1b,
                     const float* __restrict__ fc2w, const float* __restrict__ fc2b,
                     const float* __restrict__ fc3w, const float* __restrict__ fc3b,
                     float* __restrict__ out)
{
    __shared__ float hg[32 * 64];
    __shared__ float h1[32 * 32];
    __shared__ float h2[32 * 16];
    int t = threadIdx.x;  // 256
    for (int idx = t; idx < 32 * 64; idx += 256) {
        int g = idx / 64;
        hg[idx] = g_graph[idx] / fmaxf(g_graphcnt[g], 1.f);
    }
    __syncthreads();
    for (int idx = t; idx < 32 * 32; idx += 256) {
        int g = idx / 32, o = idx % 32;
        float v = fc1b[o];
        for (int i = 0; i < 64; i++) v += hg[g * 64 + i] * fc1w[i * 32 + o];
        h1[idx] = (v > 0.f) ? v : expm1f(v);
    }
    __syncthreads();
    for (int idx = t; idx < 32 * 16; idx += 256) {
        int g = idx / 16, o = idx % 16;
        float v = fc2b[o];
        for (int i = 0; i < 32; i++) v += h1[g * 32 + i] * fc2w[i * 16 + o];
        h2[idx] = (v > 0.f) ? v : expm1f(v);
    }
    __syncthreads();
    if (t < 32) {
        float v = fc3b[0];
        for (int i = 0; i < 16; i++) v += h2[t * 16 + i] * fc3w[i];
        out[t] = v;
    }
}

// ---------------- host launch ----------------
extern "C" void kernel_launch(void* const* d_in, const int* in_sizes, int n_in,
                              void* d_out, int out_size)
{
    const float* x     = (const float*)d_in[0];
    const int*   ei    = (const int*)d_in[1];
    const float* eattr = (const float*)d_in[2];
    const int*   n2s   = (const int*)d_in[3];
    const int*   s2g   = (const int*)d_in[4];
    const float* W1[3]   = {(const float*)d_in[5],  (const float*)d_in[11], (const float*)d_in[17]};
    const float* b1[3]   = {(const float*)d_in[6],  (const float*)d_in[12], (const float*)d_in[18]};
    const float* W2[3]   = {(const float*)d_in[7],  (const float*)d_in[13], (const float*)d_in[19]};
    const float* b2[3]   = {(const float*)d_in[8],  (const float*)d_in[14], (const float*)d_in[20]};
    const float* root[3] = {(const float*)d_in[9],  (const float*)d_in[15], (const float*)d_in[21]};
    const float* bias[3] = {(const float*)d_in[10], (const float*)d_in[16], (const float*)d_in[22]};
    const float* fc1w = (const float*)d_in[23];
    const float* fc1b = (const float*)d_in[24];
    const float* fc2w = (const float*)d_in[25];
    const float* fc2b = (const float*)d_in[26];
    const float* fc3w = (const float*)d_in[27];
    const float* fc3b = (const float*)d_in[28];
    float* out = (float*)d_out;

    float *xa, *xb;
    cudaGetSymbolAddress((void**)&xa, g_xa);
    cudaGetSymbolAddress((void**)&xb, g_xb);

    // dynamic smem: 4 stages. CO=64: 4*18432=73728B; CO=32: 4*14336=57344B
    static bool attr_set = false;
    if (!attr_set) {
        cudaFuncSetAttribute(k_gemm64, cudaFuncAttributeMaxDynamicSharedMemorySize, 73728);
        cudaFuncSetAttribute(k_gemm32, cudaFuncAttributeMaxDynamicSharedMemorySize, 57344);
        attr_set = true;
    }

    // prologue: fused init+bsplit, then CSR build
    k_init_bsplit<<<(BTOT + 255) / 256, 256>>>(W2[0], b2[0], root[0],
                                               W2[1], b2[1], root[1],
                                               W2[2], b2[2], root[2]);
    k_count<<<N_EDGES / 256, 256>>>(ei);
    k_scan<<<1, 1024>>>();
    k_fill<<<N_EDGES / 256, 256>>>(ei);

    const int KP[3] = {KP0, KP1, KP2};
    const int BOFF[3] = {BOFF0, BOFF1, BOFF2};
    const float* xcur = x;
    float* xnext = xa;

    for (int l = 0; l < 3; l++) {
        if (l == 0)      k_scatter<16><<<N_NODES, 128>>>(xcur, ei, eattr, W1[l], b1[l], KP[l]);
        else if (l == 1) k_scatter<32><<<N_NODES, 128>>>(xcur, ei, eattr, W1[l], b1[l], KP[l]);
        else             k_scatter<64><<<N_NODES, 128>>>(xcur, ei, eattr, W1[l], b1[l], KP[l]);

        if (l == 0)
            k_gemm32<<<N_NODES / 64, 256, 57344>>>(KP[l], BOFF[l], xnext, bias[l]);
        else
            k_gemm64<<<N_NODES / 64, 256, 73728>>>(KP[l], BOFF[l], xnext, bias[l]);

        xcur = xnext;
        xnext = (xnext == xa) ? xb : xa;
    }

    // pooling + MLP head
    k_pool1<<<(N_NODES * 64 + 255) / 256, 256>>>(xcur, n2s);
    k_pool2<<<(N_SUB * 64 + 255) / 256, 256>>>(s2g);
    k_fc<<<1, 256>>>(fc1w, fc1b, fc2w, fc2b, fc3w, fc3b, out);
}

// round 17
// speedup vs baseline: 1.2737x; 1.0071x over previous
#include <cuda_runtime.h>
#include <cuda_fp16.h>
#include <cstdint>

#define N_NODES 8192
#define N_EDGES 32768
#define HID 128
#define N_SUB 512
#define N_GRAPH 32

// K' per layer (K + 2*ci, padded to multiple of 64)
#define KP0 2112
#define KP1 4160
#define KP2 8320
// B' buffer offsets (elems)
#define BOFF0 0
#define BOFF1 67584            // 2112*32
#define BOFF2 333824           // 67584 + 4160*64
#define BTOT  866304           // 333824 + 8320*64

// ---------------- device scratch (static; no allocations) ----------------
__device__ __half g_S[8192ull * 8320];   // [n][K'] fp16
__device__ __half g_Bh[BTOT];            // [K'][co] fp16, k-major
__device__ float g_xa[N_NODES * 64];
__device__ float g_xb[N_NODES * 64];
__device__ int   g_rowptr[N_NODES + 1];
__device__ int   g_fill[N_NODES];
__device__ float g_epack[N_EDGES * 6];   // CSR-ordered edge payload: [src|attr0..4]
__device__ float g_sub[N_SUB * 64];
__device__ float g_subcnt[N_SUB];
__device__ float g_graph[N_GRAPH * 64];
__device__ float g_graphcnt[N_GRAPH];

// ---------------- PTX helpers (baseline ISA only; no arch-suffix gating) --------
__device__ __forceinline__ uint32_t smem_u32(const void* p) {
    uint32_t a;
    asm("{ .reg .u64 t; cvta.to.shared.u64 t, %1; cvt.u32.u64 %0, t; }" : "=r"(a) : "l"(p));
    return a;
}
__device__ __forceinline__ void ldsm_x4(uint32_t& r0, uint32_t& r1, uint32_t& r2,
                                        uint32_t& r3, uint32_t addr) {
    asm volatile("ldmatrix.sync.aligned.m8n8.x4.shared.b16 {%0,%1,%2,%3}, [%4];"
                 : "=r"(r0), "=r"(r1), "=r"(r2), "=r"(r3) : "r"(addr));
}
__device__ __forceinline__ void ldsm_x4t(uint32_t& r0, uint32_t& r1, uint32_t& r2,
                                         uint32_t& r3, uint32_t addr) {
    asm volatile("ldmatrix.sync.aligned.m8n8.x4.trans.shared.b16 {%0,%1,%2,%3}, [%4];"
                 : "=r"(r0), "=r"(r1), "=r"(r2), "=r"(r3) : "r"(addr));
}
__device__ __forceinline__ void mma_f16(float& d0, float& d1, float& d2, float& d3,
                                        uint32_t a0, uint32_t a1, uint32_t a2, uint32_t a3,
                                        uint32_t b0, uint32_t b1) {
    asm volatile(
        "mma.sync.aligned.m16n8k16.row.col.f32.f16.f16.f32 "
        "{%0,%1,%2,%3}, {%4,%5,%6,%7}, {%8,%9}, {%0,%1,%2,%3};"
        : "+f"(d0), "+f"(d1), "+f"(d2), "+f"(d3)
        : "r"(a0), "r"(a1), "r"(a2), "r"(a3), "r"(b0), "r"(b1));
}
#define CP_ASYNC16(dst, src) \
    asm volatile("cp.async.cg.shared.global [%0], [%1], 16;" :: "r"(dst), "l"(src))
#define CP_COMMIT() asm volatile("cp.async.commit_group;" ::: "memory")
#define CP_WAIT2()  asm volatile("cp.async.wait_group 2;" ::: "memory")

// ---------------- init + B' conversion fused (both pure writers) ----------------
__global__ void k_init_bsplit(
    const float* __restrict__ W2_0, const float* __restrict__ b2_0, const float* __restrict__ rt_0,
    const float* __restrict__ W2_1, const float* __restrict__ b2_1, const float* __restrict__ rt_1,
    const float* __restrict__ W2_2, const float* __restrict__ b2_2, const float* __restrict__ rt_2)
{
    int idx = blockIdx.x * blockDim.x + threadIdx.x;
    if (idx <= N_NODES) g_rowptr[idx] = 0;
    if (idx < N_SUB * 64)   g_sub[idx] = 0.f;
    if (idx < N_SUB)        g_subcnt[idx] = 0.f;
    if (idx < N_GRAPH * 64) g_graph[idx] = 0.f;
    if (idx < N_GRAPH)      g_graphcnt[idx] = 0.f;

    if (idx >= BTOT) return;
    int rel, ci, co, K;
    const float *W2, *b2, *rt;
    if (idx < BOFF1)      { rel = idx;         ci = 16; co = 32; K = 2048; W2 = W2_0; b2 = b2_0; rt = rt_0; }
    else if (idx < BOFF2) { rel = idx - BOFF1; ci = 32; co = 64; K = 4096; W2 = W2_1; b2 = b2_1; rt = rt_1; }
    else                  { rel = idx - BOFF2; ci = 64; co = 64; K = 8192; W2 = W2_2; b2 = b2_2; rt = rt_2; }
    int kk = rel / co, o = rel % co;
    float w;
    if (kk < K) {
        int i = kk >> 7, k = kk & 127;
        w = W2[(k * ci + i) * co + o];
    } else if (kk < K + ci) {
        w = b2[(kk - K) * co + o];
    } else if (kk < K + 2 * ci) {
        w = rt[(kk - K - ci) * co + o];
    } else {
        w = 0.f;
    }
    g_Bh[idx] = __float2half_rn(w);
}

__global__ void k_count(const int* __restrict__ ei) {
    int e = blockIdx.x * blockDim.x + threadIdx.x;
    if (e < N_EDGES) atomicAdd(&g_rowptr[ei[N_EDGES + e] + 1], 1);
}

__global__ void k_scan() {
    __shared__ int part[1024];
    int t = threadIdx.x;
    int v[8];
    int run = 0;
#pragma unroll
    for (int q = 0; q < 8; q++) { run += g_rowptr[1 + t * 8 + q]; v[q] = run; }
    part[t] = run;
    __syncthreads();
    int sum = run;
    for (int off = 1; off < 1024; off <<= 1) {
        int other = (t >= off) ? part[t - off] : 0;
        __syncthreads();
        sum += other;
        part[t] = sum;
        __syncthreads();
    }
    int add = sum - run;
#pragma unroll
    for (int q = 0; q < 8; q++) {
        int val = v[q] + add;
        int pos = 1 + t * 8 + q;
        g_rowptr[pos] = val;
        if (pos < N_NODES) g_fill[pos] = val;
    }
    if (t == 0) { g_rowptr[0] = 0; g_fill[0] = 0; }
}

// fill writes the full edge PAYLOAD in CSR order (src + 5 attrs packed)
__global__ void k_fill(const int* __restrict__ ei, const float* __restrict__ eattr) {
    int e = blockIdx.x * blockDim.x + threadIdx.x;
    if (e < N_EDGES) {
        int d = ei[N_EDGES + e];
        int src = ei[e];
        int pos = atomicAdd(&g_fill[d], 1);
        float* p = &g_epack[pos * 6];
        p[0] = __int_as_float(src);
#pragma unroll
        for (int j = 0; j < 5; j++) p[1 + j] = eattr[e * 5 + j];
    }
}

// ---------------- scatter: S'[n] = [S | xs | x | 0pad] as fp16 -------------------
// Edge payload read directly from CSR-ordered g_epack: one LDG level + shfl
// instead of eperm->ei->eattr dependent-LDG chain. Arithmetic unchanged.
template <int CI>
__global__ __launch_bounds__(128) void k_scatter(
    const float* __restrict__ xcur,
    const float* __restrict__ W1,
    const float* __restrict__ b1, int KP)
{
    constexpr int K = CI * 128;
    int n = blockIdx.x;
    int t = threadIdx.x;
    int w = t >> 5, lane = t & 31;
    __shared__ __align__(16) float sx[4][CI];
    __shared__ float sattr[4][5];

    float w1r[5];
#pragma unroll
    for (int j = 0; j < 5; j++) w1r[j] = W1[j * HID + t];
    float b1r = b1[t];

    float sacc[CI];
#pragma unroll
    for (int i = 0; i < CI; i++) sacc[i] = 0.f;
    float xsacc = 0.f;

    int beg = g_rowptr[n], end = g_rowptr[n + 1];
    for (int j0 = beg; j0 < end; j0 += 4) {
        int cnt = min(4, end - j0);
        if (w < cnt) {
            float pv = (lane < 6) ? g_epack[(j0 + w) * 6 + lane] : 0.f;
            int src = __float_as_int(__shfl_sync(0xffffffffu, pv, 0));
            if (lane >= 1 && lane < 6) sattr[w][lane - 1] = pv;
#pragma unroll
            for (int i = lane; i < CI; i += 32) sx[w][i] = xcur[src * CI + i];
        }
        __syncthreads();
        for (int c = 0; c < cnt; c++) {
            float h = b1r;
#pragma unroll
            for (int q = 0; q < 5; q++) h += sattr[c][q] * w1r[q];
            h = fmaxf(h, 0.f);
            const float4* sx4 = (const float4*)sx[c];
#pragma unroll
            for (int i4 = 0; i4 < CI / 4; i4++) {
                float4 v = sx4[i4];
                sacc[i4 * 4 + 0] += h * v.x;
                sacc[i4 * 4 + 1] += h * v.y;
                sacc[i4 * 4 + 2] += h * v.z;
                sacc[i4 * 4 + 3] += h * v.w;
            }
            if (t < CI) xsacc += sx[c][t];
        }
        __syncthreads();
    }

    size_t base = (size_t)n * KP;
#pragma unroll
    for (int i = 0; i < CI; i++)
        g_S[base + (size_t)i * HID + t] = __float2half_rn(sacc[i]);
    int ext = KP - K;
    if (t < ext) {
        float v;
        if (t < CI) v = xsacc;
        else if (t < 2 * CI) v = xcur[n * CI + (t - CI)];
        else v = 0.f;
        g_S[base + K + t] = __float2half_rn(v);
    }
}

// ---------------- GEMM CO=32 (layer 1): fp16 single product, 4-stage ring ------
__global__ __launch_bounds__(256) void k_gemm32(int KP, int boff,
                                                float* __restrict__ xnext,
                                                const float* __restrict__ bias)
{
    constexpr int CO = 32;
    constexpr int AP = 72;
    constexpr int BP = CO + 8;                 // 40
    constexpr uint32_t A_OFF = 0;
    constexpr uint32_t BH_OFF = 64 * AP * 2;   // 9216
    constexpr uint32_t STAGE = BH_OFF + 64 * BP * 2;    // 14336
    constexpr int NSTAGE = 4;

    extern __shared__ char smem[];
    const uint32_t sb = smem_u32(smem);

    const int t = threadIdx.x;
    const int wid = t >> 5, lane = t & 31;
    const int wm = wid & 3;
    const int wn = wid >> 2;
    const int m0 = blockIdx.x * 64;

    float acc[2][4];
#pragma unroll
    for (int i = 0; i < 2; i++)
#pragma unroll
        for (int j = 0; j < 4; j++) acc[i][j] = 0.f;

    const int nIter = KP / 64;

    auto issue = [&](int sg, int kt) {
        uint32_t s0 = sb + sg * STAGE;
#pragma unroll
        for (int p = 0; p < 2; p++) {
            int c = t + 256 * p;
            int row = c >> 3, cc = c & 7;
            uint32_t d = s0 + (uint32_t)(row * AP + cc * 8) * 2u;
            CP_ASYNC16(d + A_OFF, &g_S[(size_t)(m0 + row) * KP + kt + cc * 8]);
        }
        {
            int c = t;
            int row = c >> 2, cc = c & 3;
            uint32_t d = s0 + (uint32_t)(row * BP + cc * 8) * 2u;
            CP_ASYNC16(d + BH_OFF, &g_Bh[boff + (size_t)(kt + row) * CO + cc * 8]);
        }
    };

#pragma unroll
    for (int s = 0; s < NSTAGE - 1; s++) { issue(s, s * 64); CP_COMMIT(); }

    for (int it = 0; it < nIter; it++) {
        CP_WAIT2();
        __syncthreads();
        if (it + NSTAGE - 1 < nIter) issue((it + NSTAGE - 1) & (NSTAGE - 1),
                                           (it + NSTAGE - 1) * 64);
        CP_COMMIT();

        uint32_t s0 = sb + (it & (NSTAGE - 1)) * STAGE;
#pragma unroll
        for (int ks = 0; ks < 4; ks++) {
            uint32_t a_off = s0 + (uint32_t)((wm * 16 + (lane & 15)) * AP +
                                             ks * 16 + (lane >> 4) * 8) * 2u;
            uint32_t a0, a1, a2, a3;
            ldsm_x4(a0, a1, a2, a3, a_off + A_OFF);
            {
                int nb = wn * 16;
                uint32_t b_off = s0 + (uint32_t)((ks * 16 + (lane & 15)) * BP +
                                                 nb + (lane >> 4) * 8) * 2u;
                uint32_t bh0, bh1, bh2, bh3;
                ldsm_x4t(bh0, bh1, bh2, bh3, b_off + BH_OFF);
                mma_f16(acc[0][0], acc[0][1], acc[0][2], acc[0][3], a0, a1, a2, a3, bh0, bh1);
                mma_f16(acc[1][0], acc[1][1], acc[1][2], acc[1][3], a0, a1, a2, a3, bh2, bh3);
            }
        }
    }

    const int row0 = lane >> 2;
    const int col0 = (lane & 3) * 2;
#pragma unroll
    for (int nt = 0; nt < 2; nt++) {
        int m = m0 + wm * 16 + row0;
        int c = wn * 16 + nt * 8 + col0;
        float b0 = bias[c], b1v = bias[c + 1];
        float v0 = acc[nt][0] + b0, v1 = acc[nt][1] + b1v;
        float v2 = acc[nt][2] + b0, v3 = acc[nt][3] + b1v;
        v0 = (v0 > 0.f) ? v0 : expm1f(v0);
        v1 = (v1 > 0.f) ? v1 : expm1f(v1);
        v2 = (v2 > 0.f) ? v2 : expm1f(v2);
        v3 = (v3 > 0.f) ? v3 : expm1f(v3);
        *(float2*)&xnext[(size_t)m * CO + c] = make_float2(v0, v1);
        *(float2*)&xnext[(size_t)(m + 8) * CO + c] = make_float2(v2, v3);
    }
}

// ---------------- GEMM CO=64: m32n32 warp tile, 2-way split-K, 4-stage ring ----
__global__ __launch_bounds__(256) void k_gemm64(int KP, int boff,
                                                float* __restrict__ xnext,
                                                const float* __restrict__ bias)
{
    constexpr int CO = 64;
    constexpr int AP = 72;
    constexpr int BP = CO + 8;                 // 72
    constexpr uint32_t A_OFF = 0;
    constexpr uint32_t BH_OFF = 64 * AP * 2;   // 9216
    constexpr uint32_t STAGE = BH_OFF + 64 * BP * 2;    // 18432
    constexpr int NSTAGE = 4;

    extern __shared__ char smem[];
    const uint32_t sb = smem_u32(smem);

    const int t = threadIdx.x;
    const int wid = t >> 5, lane = t & 31;
    const int wk = wid >> 2;
    const int wm = (wid >> 1) & 1;
    const int wn = wid & 1;
    const int m0 = blockIdx.x * 64;

    float acc[8][4];
#pragma unroll
    for (int i = 0; i < 8; i++)
#pragma unroll
        for (int j = 0; j < 4; j++) acc[i][j] = 0.f;

    const int nIter = KP / 64;

    auto issue = [&](int sg, int kt) {
        uint32_t s0 = sb + sg * STAGE;
#pragma unroll
        for (int p = 0; p < 2; p++) {
            int c = t + 256 * p;
            int row = c >> 3, cc = c & 7;
            uint32_t d = s0 + (uint32_t)(row * AP + cc * 8) * 2u;
            CP_ASYNC16(d + A_OFF, &g_S[(size_t)(m0 + row) * KP + kt + cc * 8]);
        }
#pragma unroll
        for (int p = 0; p < 2; p++) {
            int c = t + 256 * p;
            int row = c >> 3, cc = c & 7;
            uint32_t d = s0 + (uint32_t)(row * BP + cc * 8) * 2u;
            CP_ASYNC16(d + BH_OFF, &g_Bh[boff + (size_t)(kt + row) * CO + cc * 8]);
        }
    };

#pragma unroll
    for (int s = 0; s < NSTAGE - 1; s++) { issue(s, s * 64); CP_COMMIT(); }

    for (int it = 0; it < nIter; it++) {
        CP_WAIT2();
        __syncthreads();
        if (it + NSTAGE - 1 < nIter) issue((it + NSTAGE - 1) & (NSTAGE - 1),
                                           (it + NSTAGE - 1) * 64);
        CP_COMMIT();

        uint32_t s0 = sb + (it & (NSTAGE - 1)) * STAGE;
#pragma unroll
        for (int ks2 = 0; ks2 < 2; ks2++) {
            int kk = wk * 32 + ks2 * 16;
            uint32_t ah[2][4];
#pragma unroll
            for (int mt = 0; mt < 2; mt++) {
                uint32_t a_off = s0 + (uint32_t)((wm * 32 + mt * 16 + (lane & 15)) * AP +
                                                 kk + (lane >> 4) * 8) * 2u;
                ldsm_x4(ah[mt][0], ah[mt][1], ah[mt][2], ah[mt][3], a_off + A_OFF);
            }
            uint32_t bh[2][4];
#pragma unroll
            for (int np = 0; np < 2; np++) {
                int nb = wn * 32 + np * 16;
                uint32_t b_off = s0 + (uint32_t)((kk + (lane & 15)) * BP +
                                                 nb + (lane >> 4) * 8) * 2u;
                ldsm_x4t(bh[np][0], bh[np][1], bh[np][2], bh[np][3], b_off + BH_OFF);
            }
#pragma unroll
            for (int mt = 0; mt < 2; mt++) {
#pragma unroll
                for (int np = 0; np < 2; np++) {
                    float* c0 = acc[mt * 4 + np * 2 + 0];
                    float* c1 = acc[mt * 4 + np * 2 + 1];
                    mma_f16(c0[0], c0[1], c0[2], c0[3],
                            ah[mt][0], ah[mt][1], ah[mt][2], ah[mt][3], bh[np][0], bh[np][1]);
                    mma_f16(c1[0], c1[1], c1[2], c1[3],
                            ah[mt][0], ah[mt][1], ah[mt][2], ah[mt][3], bh[np][2], bh[np][3]);
                }
            }
        }
    }

    // ---- split-K reduction: wk=1 warps dump acc to smem, wk=0 warps add ----
    __syncthreads();
    {
        float* red = (float*)smem;
        int pair = wm * 2 + wn;
        if (wk == 1) {
#pragma unroll
            for (int j = 0; j < 8; j++)
#pragma unroll
                for (int q = 0; q < 4; q++)
                    red[pair * 1024 + (j * 4 + q) * 32 + lane] = acc[j][q];
        }
        __syncthreads();
        if (wk == 0) {
#pragma unroll
            for (int j = 0; j < 8; j++)
#pragma unroll
                for (int q = 0; q < 4; q++)
                    acc[j][q] += red[pair * 1024 + (j * 4 + q) * 32 + lane];
        }
    }

    if (wk == 0) {
        const int row0 = lane >> 2;
        const int col0 = (lane & 3) * 2;
#pragma unroll
        for (int mt = 0; mt < 2; mt++) {
#pragma unroll
            for (int np = 0; np < 2; np++) {
#pragma unroll
                for (int h = 0; h < 2; h++) {
                    float* a = acc[mt * 4 + np * 2 + h];
                    int m = m0 + wm * 32 + mt * 16 + row0;
                    int c = wn * 32 + np * 16 + h * 8 + col0;
                    float b0 = bias[c], b1v = bias[c + 1];
                    float v0 = a[0] + b0, v1 = a[1] + b1v;
                    float v2 = a[2] + b0, v3 = a[3] + b1v;
                    v0 = (v0 > 0.f) ? v0 : expm1f(v0);
                    v1 = (v1 > 0.f) ? v1 : expm1f(v1);
                    v2 = (v2 > 0.f) ? v2 : expm1f(v2);
                    v3 = (v3 > 0.f) ? v3 : expm1f(v3);
                    *(float2*)&xnext[(size_t)m * CO + c] = make_float2(v0, v1);
                    *(float2*)&xnext[(size_t)(m + 8) * CO + c] = make_float2(v2, v3);
                }
            }
        }
    }
}

// ---------------- pooling ----------------
__global__ void k_pool1(const float* __restrict__ x3, const int* __restrict__ n2s) {
    int idx = blockIdx.x * blockDim.x + threadIdx.x;
    if (idx >= N_NODES * 64) return;
    int n = idx / 64, o = idx % 64;
    int s = n2s[n];
    atomicAdd(&g_sub[s * 64 + o], x3[idx]);
    if (o == 0) atomicAdd(&g_subcnt[s], 1.f);
}

__global__ void k_pool2(const int* __restrict__ s2g) {
    int idx = blockIdx.x * blockDim.x + threadIdx.x;
    if (idx >= N_SUB * 64) return;
    int s = idx / 64, o = idx % 64;
    float m = g_sub[idx] / fmaxf(g_subcnt[s], 1.f);
    int g = s2g[s];
    atomicAdd(&g_graph[g * 64 + o], m);
    if (o == 0) atomicAdd(&g_graphcnt[g], 1.f);
}

// ---------------- final MLP (single block) ----------------
__global__ void k_fc(const float* __restrict__ fc1w, const float* __restrict__ fc1b,
                     const float* __restrict__ fc2w, const float* __restrict__ fc2b,
                     const float* __restrict__ fc3w, const float* __restrict__ fc3b,
                     float* __restrict__ out)
{
    __shared__ float hg[32 * 64];
    __shared__ float h1[32 * 32];
    __shared__ float h2[32 * 16];
    int t = threadIdx.x;  // 256
    for (int idx = t; idx < 32 * 64; idx += 256) {
        int g = idx / 64;
        hg[idx] = g_graph[idx] / fmaxf(g_graphcnt[g], 1.f);
    }
    __syncthreads();
    for (int idx = t; idx < 32 * 32; idx += 256) {
        int g = idx / 32, o = idx % 32;
        float v = fc1b[o];
        for (int i = 0; i < 64; i++) v += hg[g * 64 + i] * fc1w[i * 32 + o];
        h1[idx] = (v > 0.f) ? v : expm1f(v);
    }
    __syncthreads();
    for (int idx = t; idx < 32 * 16; idx += 256) {
        int g = idx / 16, o = idx % 16;
        float v = fc2b[o];
        for (int i = 0; i < 32; i++) v += h1[g * 32 + i] * fc2w[i * 16 + o];
        h2[idx] = (v > 0.f) ? v : expm1f(v);
    }
    __syncthreads();
    if (t < 32) {
        float v = fc3b[0];
        for (int i = 0; i < 16; i++) v += h2[t * 16 + i] * fc3w[i];
        out[t] = v;
    }
}

// ---------------- host launch ----------------
extern "C" void kernel_launch(void* const* d_in, const int* in_sizes, int n_in,
                              void* d_out, int out_size)
{
    const float* x     = (const float*)d_in[0];
    const int*   ei    = (const int*)d_in[1];
    const float* eattr = (const float*)d_in[2];
    const int*   n2s   = (const int*)d_in[3];
    const int*   s2g   = (const int*)d_in[4];
    const float* W1[3]   = {(const float*)d_in[5],  (const float*)d_in[11], (const float*)d_in[17]};
    const float* b1[3]   = {(const float*)d_in[6],  (const float*)d_in[12], (const float*)d_in[18]};
    const float* W2[3]   = {(const float*)d_in[7],  (const float*)d_in[13], (const float*)d_in[19]};
    const float* b2[3]   = {(const float*)d_in[8],  (const float*)d_in[14], (const float*)d_in[20]};
    const float* root[3] = {(const float*)d_in[9],  (const float*)d_in[15], (const float*)d_in[21]};
    const float* bias[3] = {(const float*)d_in[10], (const float*)d_in[16], (const float*)d_in[22]};
    const float* fc1w = (const float*)d_in[23];
    const float* fc1b = (const float*)d_in[24];
    const float* fc2w = (const float*)d_in[25];
    const float* fc2b = (const float*)d_in[26];
    const float* fc3w = (const float*)d_in[27];
    const float* fc3b = (const float*)d_in[28];
    float* out = (float*)d_out;

    float *xa, *xb;
    cudaGetSymbolAddress((void**)&xa, g_xa);
    cudaGetSymbolAddress((void**)&xb, g_xb);

    // dynamic smem: 4 stages. CO=64: 4*18432=73728B; CO=32: 4*14336=57344B
    static bool attr_set = false;
    if (!attr_set) {
        cudaFuncSetAttribute(k_gemm64, cudaFuncAttributeMaxDynamicSharedMemorySize, 73728);
        cudaFuncSetAttribute(k_gemm32, cudaFuncAttributeMaxDynamicSharedMemorySize, 57344);
        attr_set = true;
    }

    // prologue: fused init+bsplit, then CSR build (fill writes packed payload)
    k_init_bsplit<<<(BTOT + 255) / 256, 256>>>(W2[0], b2[0], root[0],
                                               W2[1], b2[1], root[1],
                                               W2[2], b2[2], root[2]);
    k_count<<<N_EDGES / 256, 256>>>(ei);
    k_scan<<<1, 1024>>>();
    k_fill<<<N_EDGES / 256, 256>>>(ei, eattr);

    const int KP[3] = {KP0, KP1, KP2};
    const int BOFF[3] = {BOFF0, BOFF1, BOFF2};
    const float* xcur = x;
    float* xnext = xa;

    for (int l = 0; l < 3; l++) {
        if (l == 0)      k_scatter<16><<<N_NODES, 128>>>(xcur, W1[l], b1[l], KP[l]);
        else if (l == 1) k_scatter<32><<<N_NODES, 128>>>(xcur, W1[l], b1[l], KP[l]);
        else             k_scatter<64><<<N_NODES, 128>>>(xcur, W1[l], b1[l], KP[l]);

        if (l == 0)
            k_gemm32<<<N_NODES / 64, 256, 57344>>>(KP[l], BOFF[l], xnext, bias[l]);
        else
            k_gemm64<<<N_NODES / 64, 256, 73728>>>(KP[l], BOFF[l], xnext, bias[l]);

        xcur = xnext;
        xnext = (xnext == xa) ? xb : xa;
    }

    // pooling + MLP head
    k_pool1<<<(N_NODES * 64 + 255) / 256, 256>>>(xcur, n2s);
    k_pool2<<<(N_SUB * 64 + 255) / 256, 256>>>(s2g);
    k_fc<<<1, 256>>>(fc1w, fc1b, fc2w, fc2b, fc3w, fc3b, out);
}